// round 11
// baseline (speedup 1.0000x reference)
#include <cuda_runtime.h>
#include <cuda_bf16.h>
#include <cstdint>

#define NN   131072
#define EE   1048576
#define HH   128
#define VV   30000
#define VPAD 30080     // 235 * 128
#define BBG  512
#define PPG  32
#define NH   (NN*HH)
#define NKEY (4*NN)

// ---------------- static device scratch ----------------
__device__ float g_ptab[VPAD * HH];    // projected embedding table
__device__ float g_h[NH];
__device__ float g_h2[NH];
__device__ uint16_t g_mh[4ULL * NH];   // mailbox hi (bf16)
__device__ uint16_t g_ml[4ULL * NH];   // mailbox lo (bf16)
__device__ uint16_t g_wh[2 * 4 * HH * HH];  // W_r hi
__device__ uint16_t g_wl[2 * 4 * HH * HH];  // W_r lo
__device__ float g_pool[BBG * HH];
__device__ float g_tp[BBG * HH];
__device__ float g_wbt[HH * HH];
// (type,dst)-keyed CSR
__device__ int  g_cnt[NKEY];
__device__ int  g_off[NKEY + 1];
__device__ int  g_cur[NKEY];
__device__ int  g_bsum[512];
__device__ int2 g_rec[EE];             // {src, norm bits}

// ---------------- helpers ----------------
__device__ __forceinline__ uint32_t smem_u32(const void* p) {
    uint32_t a;
    asm("{ .reg .u64 t; cvta.to.shared.u64 t, %1; cvt.u32.u64 %0, t; }" : "=r"(a) : "l"(p));
    return a;
}
__device__ __forceinline__ void ldsm_x4(uint32_t r[4], uint32_t addr) {
    asm volatile("ldmatrix.sync.aligned.m8n8.x4.shared.b16 {%0,%1,%2,%3}, [%4];"
                 : "=r"(r[0]), "=r"(r[1]), "=r"(r[2]), "=r"(r[3]) : "r"(addr));
}
__device__ __forceinline__ void ldsm_x4_t(uint32_t r[4], uint32_t addr) {
    asm volatile("ldmatrix.sync.aligned.m8n8.x4.trans.shared.b16 {%0,%1,%2,%3}, [%4];"
                 : "=r"(r[0]), "=r"(r[1]), "=r"(r[2]), "=r"(r[3]) : "r"(addr));
}
__device__ __forceinline__ void mma_bf16(float* c, const uint32_t a[4], const uint32_t* b) {
    asm volatile(
        "mma.sync.aligned.m16n8k16.row.col.f32.bf16.bf16.f32 "
        "{%0,%1,%2,%3}, {%4,%5,%6,%7}, {%8,%9}, {%0,%1,%2,%3};"
        : "+f"(c[0]), "+f"(c[1]), "+f"(c[2]), "+f"(c[3])
        : "r"(a[0]), "r"(a[1]), "r"(a[2]), "r"(a[3]), "r"(b[0]), "r"(b[1]));
}
__device__ __forceinline__ void split2(float a, float b, uint32_t& hi, uint32_t& lo) {
    __nv_bfloat16 ha = __float2bfloat16_rn(a);
    __nv_bfloat16 hb = __float2bfloat16_rn(b);
    __nv_bfloat16 la = __float2bfloat16_rn(a - __bfloat162float(ha));
    __nv_bfloat16 lb = __float2bfloat16_rn(b - __bfloat162float(hb));
    hi = (uint32_t)__bfloat16_as_ushort(ha) | ((uint32_t)__bfloat16_as_ushort(hb) << 16);
    lo = (uint32_t)__bfloat16_as_ushort(la) | ((uint32_t)__bfloat16_as_ushort(lb) << 16);
}
__device__ __forceinline__ void cp16_ef(uint32_t smem, const void* g, uint64_t pol) {
    asm volatile("cp.async.cg.shared.global.L2::cache_hint [%0], [%1], 16, %2;"
                 :: "r"(smem), "l"(g), "l"(pol));
}
__device__ __forceinline__ void cp16(uint32_t smem, const void* g) {
    asm volatile("cp.async.cg.shared.global [%0], [%1], 16;" :: "r"(smem), "l"(g));
}

// ---------------- CSR build ((type,dst)-keyed) ----------------
__global__ void k_count(const int* __restrict__ dst, const int* __restrict__ et) {
    int e = blockIdx.x * blockDim.x + threadIdx.x;
    if (e >= EE) return;
    atomicAdd(&g_cnt[et[e] * NN + dst[e]], 1);
}

__global__ void k_scan1() {   // 512 blocks x 256 thr; 1024 elems/block
    __shared__ int s[256];
    int t = threadIdx.x;
    int4 v = *(const int4*)(g_cnt + blockIdx.x * 1024 + t * 4);
    s[t] = v.x + v.y + v.z + v.w;
    __syncthreads();
    for (int o = 128; o > 0; o >>= 1) {
        if (t < o) s[t] += s[t + o];
        __syncthreads();
    }
    if (t == 0) g_bsum[blockIdx.x] = s[0];
}

__global__ void k_scan2() {   // 1 block, 512 thr
    __shared__ int s[512];
    int t = threadIdx.x;
    int mine = g_bsum[t];
    s[t] = mine;
    __syncthreads();
    for (int o = 1; o < 512; o <<= 1) {
        int add = (t >= o) ? s[t - o] : 0;
        __syncthreads();
        s[t] += add;
        __syncthreads();
    }
    g_bsum[t] = s[t] - mine;
}

__global__ void k_scan3() {   // 512 blocks x 256 thr
    __shared__ int s[256];
    int t = threadIdx.x;
    int base = blockIdx.x * 1024 + t * 4;
    int4 v = *(const int4*)(g_cnt + base);
    int tsum = v.x + v.y + v.z + v.w;
    s[t] = tsum;
    __syncthreads();
    for (int o = 1; o < 256; o <<= 1) {
        int add = (t >= o) ? s[t - o] : 0;
        __syncthreads();
        s[t] += add;
        __syncthreads();
    }
    int o0 = s[t] - tsum + g_bsum[blockIdx.x];
    int o1 = o0 + v.x, o2 = o1 + v.y, o3 = o2 + v.z;
    *(int4*)(g_off + base) = make_int4(o0, o1, o2, o3);
    *(int4*)(g_cur + base) = make_int4(o0, o1, o2, o3);
    if (base + 4 == NKEY) g_off[NKEY] = o3 + v.w;
}

__global__ void k_fill(const int* __restrict__ src, const int* __restrict__ dst,
                       const int* __restrict__ et,  const float* __restrict__ norm) {
    int e = blockIdx.x * blockDim.x + threadIdx.x;
    if (e >= EE) return;
    int p = atomicAdd(&g_cur[et[e] * NN + dst[e]], 1);
    g_rec[p] = make_int2(src[e], __float_as_int(norm[e]));
}

// ---------------- weight split ----------------
__global__ void k_wsplit(const float* __restrict__ Wr) {
    int i = blockIdx.x * blockDim.x + threadIdx.x;
    float v = Wr[i];
    __nv_bfloat16 h = __float2bfloat16_rn(v);
    g_wh[i] = __bfloat16_as_ushort(h);
    g_wl[i] = __bfloat16_as_ushort(__float2bfloat16_rn(v - __bfloat162float(h)));
}

// ---------------- projected table: ptab = emb_table @ Wt[:128] ----------------
#define SM_AHI 0
#define SM_ALO 18432
#define SM_BHI 36864
#define SM_BLO 54272
#define SM_TOT 71680

__global__ void __launch_bounds__(256, 2) k_proj(
    const float* __restrict__ A, const float* __restrict__ Wt)
{
    extern __shared__ char smem[];
    uint32_t s0 = smem_u32(smem);
    int tid = threadIdx.x, wid = tid >> 5, lane = tid & 31;
    int row0 = blockIdx.x * 128;
    int warp_m = wid & 1, warp_n = wid >> 1;

    float c[4][4][4];
#pragma unroll
    for (int i = 0; i < 4; i++)
#pragma unroll
        for (int j = 0; j < 4; j++)
#pragma unroll
            for (int q = 0; q < 4; q++) c[i][j][q] = 0.0f;

    for (int ch = 0; ch < 2; ch++) {
        if (tid < 128) {
#pragma unroll
            for (int p = 0; p < 16; p++) {
                int e = p * 128 + tid;
                int r = e >> 4, c4 = e & 15;
                int rg = min(row0 + r, VV - 1);
                float4 v = *(const float4*)(A + (size_t)rg * HH + ch * 64 + c4 * 4);
                uint32_t h0, l0, h1, l1;
                split2(v.x, v.y, h0, l0);
                split2(v.z, v.w, h1, l1);
                uint32_t off = (uint32_t)r * 144 + c4 * 8;
                *(uint2*)(smem + SM_AHI + off) = make_uint2(h0, h1);
                *(uint2*)(smem + SM_ALO + off) = make_uint2(l0, l1);
            }
        } else {
            int t = tid - 128;
            const float* gb = Wt + (size_t)(ch * 64) * HH;
#pragma unroll
            for (int p = 0; p < 16; p++) {
                int e = p * 128 + t;
                int k = e >> 5, c4 = e & 31;
                float4 v = *(const float4*)(gb + (size_t)k * HH + c4 * 4);
                uint32_t h0, l0, h1, l1;
                split2(v.x, v.y, h0, l0);
                split2(v.z, v.w, h1, l1);
                uint32_t off = (uint32_t)k * 272 + c4 * 8;
                *(uint2*)(smem + SM_BHI + off) = make_uint2(h0, h1);
                *(uint2*)(smem + SM_BLO + off) = make_uint2(l0, l1);
            }
        }
        __syncthreads();

#pragma unroll
        for (int ks = 0; ks < 4; ks++) {
            uint32_t ah[4][4], al[4][4];
#pragma unroll
            for (int mt = 0; mt < 4; mt++) {
                uint32_t row  = warp_m * 64 + mt * 16 + (lane & 15);
                uint32_t addr = s0 + SM_AHI + row * 144 + ks * 32 + ((lane >> 4) << 4);
                ldsm_x4(ah[mt], addr);
                ldsm_x4(al[mt], addr + (SM_ALO - SM_AHI));
            }
#pragma unroll
            for (int np = 0; np < 2; np++) {
                uint32_t kk   = ks * 16 + (lane & 15);
                uint32_t col  = warp_n * 32 + np * 16 + ((lane >> 4) & 1) * 8;
                uint32_t addr = s0 + SM_BHI + kk * 272 + col * 2;
                uint32_t bh[4], bl[4];
                ldsm_x4_t(bh, addr);
                ldsm_x4_t(bl, addr + (SM_BLO - SM_BHI));
#pragma unroll
                for (int mt = 0; mt < 4; mt++) {
                    mma_bf16(c[mt][np * 2],     ah[mt], bh);
                    mma_bf16(c[mt][np * 2],     al[mt], bh);
                    mma_bf16(c[mt][np * 2],     ah[mt], bl);
                    mma_bf16(c[mt][np * 2 + 1], ah[mt], bh + 2);
                    mma_bf16(c[mt][np * 2 + 1], al[mt], bh + 2);
                    mma_bf16(c[mt][np * 2 + 1], ah[mt], bl + 2);
                }
            }
        }
        __syncthreads();
    }

#pragma unroll
    for (int mt = 0; mt < 4; mt++) {
#pragma unroll
        for (int nt = 0; nt < 4; nt++) {
            int col = warp_n * 32 + nt * 8 + (lane & 3) * 2;
#pragma unroll
            for (int half = 0; half < 2; half++) {
                long row = row0 + warp_m * 64 + mt * 16 + (lane >> 2) + half * 8;
                if (row < VV)
                    *(float2*)(g_ptab + row * HH + col) =
                        make_float2(c[mt][nt][half * 2 + 0], c[mt][nt][half * 2 + 1]);
            }
        }
    }
}

// ---------------- init: h0 directly from ptab (warp per node, type-0 CSR) -------
__global__ void k_init2(const int* __restrict__ gid, const int* __restrict__ spo,
                        const int* __restrict__ acc_, const int* __restrict__ pre,
                        const float* __restrict__ Wt, const float* __restrict__ bt,
                        float* __restrict__ hout)
{
    __shared__ float sw[768];
    for (int i = threadIdx.x; i < 768; i += blockDim.x)
        sw[i] = (i < 640) ? Wt[(size_t)(128 + (i >> 7)) * HH + (i & 127)] : bt[i - 640];
    __syncthreads();

    int node = (blockIdx.x * blockDim.x + threadIdx.x) >> 5;
    int lane = threadIdx.x & 31;
    if (node >= NN) return;
    int s0 = spo[node * 3 + 0];
    int s1 = spo[node * 3 + 1];
    int s2 = spo[node * 3 + 2];
    int beg = g_off[node], end = g_off[node + 1];   // type-0 segment only

    float4 e4;
    if ((s0 + s2) > 0 && end > beg) {
        float4 a = make_float4(0.f, 0.f, 0.f, 0.f);
        for (int base = beg; base < end; base += 32) {
            int n = min(32, end - base);
            int2 r = (base + lane < end) ? __ldcs(&g_rec[base + lane]) : make_int2(0, 0);
            for (int i = 0; i < n; i++) {
                int rx = __shfl_sync(0xffffffffu, r.x, i);
                int rn = __shfl_sync(0xffffffffu, r.y, i);
                float nw = __int_as_float(rn);
                float4 hv = ((const float4*)g_ptab)[(size_t)gid[rx] * 32 + lane];
                a.x += hv.x * nw; a.y += hv.y * nw;
                a.z += hv.z * nw; a.w += hv.w * nw;
            }
        }
        e4 = a;
    } else {
        e4 = ((const float4*)g_ptab)[(size_t)gid[node] * 32 + lane];
    }

    float cf0 = (float)s0, cf1 = (float)s1, cf2 = (float)s2;
    float cf3 = (float)acc_[node], cf4 = (float)pre[node];
    int col = lane * 4;
#pragma unroll
    for (int q = 0; q < 4; q++) {
        float add = sw[640 + col + q]
                  + cf0 * sw[col + q]       + cf1 * sw[128 + col + q]
                  + cf2 * sw[256 + col + q] + cf3 * sw[384 + col + q]
                  + cf4 * sw[512 + col + q];
        (&e4.x)[q] += add;
    }
    ((float4*)hout)[(size_t)node * 32 + lane] = e4;
}

// ---------------- gather-first: per-type segments, streaming mailbox writes -----
__global__ void k_gather4(const float* __restrict__ h)
{
    int node = (blockIdx.x * blockDim.x + threadIdx.x) >> 5;
    int lane = threadIdx.x & 31;
    if (node >= NN) return;
    size_t o = (size_t)node * 32 + lane;

#pragma unroll
    for (int t = 0; t < 4; t++) {
        int beg = g_off[t * NN + node], end = g_off[t * NN + node + 1];
        float4 a = make_float4(0.f, 0.f, 0.f, 0.f);
        for (int base = beg; base < end; base += 32) {
            int n = min(32, end - base);
            int2 r = (base + lane < end) ? __ldcs(&g_rec[base + lane]) : make_int2(0, 0);
            for (int i = 0; i < n; i++) {
                int rx = __shfl_sync(0xffffffffu, r.x, i);
                int rn = __shfl_sync(0xffffffffu, r.y, i);
                float nw = __int_as_float(rn);
                float4 v = *(const float4*)(h + (size_t)rx * HH + lane * 4);
                a.x += v.x * nw; a.y += v.y * nw;
                a.z += v.z * nw; a.w += v.w * nw;
            }
        }
        uint32_t h0, l0, h1, l1;
        split2(a.x, a.y, h0, l0);
        split2(a.z, a.w, h1, l1);
        unsigned long long ph = (unsigned long long)h0 | ((unsigned long long)h1 << 32);
        unsigned long long pl = (unsigned long long)l0 | ((unsigned long long)l1 << 32);
        __stcs((unsigned long long*)(g_mh + (size_t)t * NH) + o, ph);
        __stcs((unsigned long long*)(g_ml + (size_t)t * NH) + o, pl);
    }
}

// ---------------- layer GEMM: cp.async double-buffered, evict-first A --------
#define GL_AHI 0
#define GL_ALO 10240
#define GL_BHI 20480
#define GL_BLO 29184
#define GL_BUF 37888
#define GL_TOT 75776

__global__ void __launch_bounds__(256, 2) k_gemm_l(
    const uint16_t* __restrict__ mh, const uint16_t* __restrict__ ml,
    const uint16_t* __restrict__ wh, const uint16_t* __restrict__ wl,
    const float* __restrict__ bias, const float* __restrict__ resid,
    float* __restrict__ C)
{
    extern __shared__ char smem[];
    uint32_t s0 = smem_u32(smem);
    int tid = threadIdx.x, wid = tid >> 5, lane = tid & 31;
    int row0 = blockIdx.x * 128;
    int warp_m = wid & 1, warp_n = wid >> 1;

    uint64_t pol;
    asm("createpolicy.fractional.L2::evict_first.b64 %0, 1.0;" : "=l"(pol));

    float c[4][4][4];
#pragma unroll
    for (int i = 0; i < 4; i++)
#pragma unroll
        for (int j = 0; j < 4; j++)
#pragma unroll
            for (int q = 0; q < 4; q++) c[i][j][q] = 0.0f;

    auto load_chunk = [&](int ch, int buf) {
        int t = ch >> 2, sub = ch & 3;
        const uint16_t* mhb = mh + (size_t)t * NH + (size_t)row0 * HH + sub * 32;
        const uint16_t* mlb = ml + (size_t)t * NH + (size_t)row0 * HH + sub * 32;
        const uint16_t* whb = wh + (size_t)t * HH * HH + (size_t)(sub * 32) * HH;
        const uint16_t* wlb = wl + (size_t)t * HH * HH + (size_t)(sub * 32) * HH;
        uint32_t sb = s0 + buf * GL_BUF;
#pragma unroll
        for (int q = 0; q < 2; q++) {
            int s = q * 256 + tid;
            int r = s >> 2, part = s & 3;
            cp16_ef(sb + GL_AHI + r * 80 + part * 16, mhb + (size_t)r * HH + part * 8, pol);
            cp16_ef(sb + GL_ALO + r * 80 + part * 16, mlb + (size_t)r * HH + part * 8, pol);
        }
#pragma unroll
        for (int q = 0; q < 2; q++) {
            int s = q * 256 + tid;
            int r = s >> 4, part = s & 15;
            cp16(sb + GL_BHI + r * 272 + part * 16, whb + (size_t)r * HH + part * 8);
            cp16(sb + GL_BLO + r * 272 + part * 16, wlb + (size_t)r * HH + part * 8);
        }
    };

    load_chunk(0, 0);
    asm volatile("cp.async.commit_group;" ::: "memory");

    for (int ch = 0; ch < 16; ch++) {
        if (ch + 1 < 16) {
            load_chunk(ch + 1, (ch + 1) & 1);
            asm volatile("cp.async.commit_group;" ::: "memory");
            asm volatile("cp.async.wait_group 1;" ::: "memory");
        } else {
            asm volatile("cp.async.wait_group 0;" ::: "memory");
        }
        __syncthreads();

        uint32_t sb = s0 + (ch & 1) * GL_BUF;
#pragma unroll
        for (int ks = 0; ks < 2; ks++) {
            uint32_t ah[4][4], al[4][4];
#pragma unroll
            for (int mt = 0; mt < 4; mt++) {
                uint32_t row  = warp_m * 64 + mt * 16 + (lane & 15);
                uint32_t addr = sb + GL_AHI + row * 80 + ks * 32 + ((lane >> 4) << 4);
                ldsm_x4(ah[mt], addr);
                ldsm_x4(al[mt], addr + (GL_ALO - GL_AHI));
            }
#pragma unroll
            for (int np = 0; np < 2; np++) {
                uint32_t kk   = ks * 16 + (lane & 15);
                uint32_t col  = warp_n * 32 + np * 16 + ((lane >> 4) & 1) * 8;
                uint32_t addr = sb + GL_BHI + kk * 272 + col * 2;
                uint32_t bh[4], bl[4];
                ldsm_x4_t(bh, addr);
                ldsm_x4_t(bl, addr + (GL_BLO - GL_BHI));
#pragma unroll
                for (int mt = 0; mt < 4; mt++) {
                    mma_bf16(c[mt][np * 2],     ah[mt], bh);
                    mma_bf16(c[mt][np * 2],     al[mt], bh);
                    mma_bf16(c[mt][np * 2],     ah[mt], bl);
                    mma_bf16(c[mt][np * 2 + 1], ah[mt], bh + 2);
                    mma_bf16(c[mt][np * 2 + 1], al[mt], bh + 2);
                    mma_bf16(c[mt][np * 2 + 1], ah[mt], bl + 2);
                }
            }
        }
        __syncthreads();
    }

#pragma unroll
    for (int mt = 0; mt < 4; mt++) {
#pragma unroll
        for (int nt = 0; nt < 4; nt++) {
            int col = warp_n * 32 + nt * 8 + (lane & 3) * 2;
            float2 bv = *(const float2*)(bias + col);
#pragma unroll
            for (int half = 0; half < 2; half++) {
                long row  = row0 + warp_m * 64 + mt * 16 + (lane >> 2) + half * 8;
                long base = row * HH + col;
                float2 v;
                v.x = fmaxf(c[mt][nt][half * 2 + 0] + bv.x, 0.f);
                v.y = fmaxf(c[mt][nt][half * 2 + 1] + bv.y, 0.f);
                if (resid) {
                    float2 rr = __ldcs((const float2*)(resid + base));
                    v.x += rr.x; v.y += rr.y;
                }
                *(float2*)(C + base) = v;
            }
        }
    }
}

// ---------------- head kernels ----------------
__global__ void k_transpose(const float* __restrict__ Wb) {
    int idx = blockIdx.x * blockDim.x + threadIdx.x;
    if (idx >= HH * HH) return;
    int r = idx >> 7, c = idx & 127;
    g_wbt[c * HH + r] = Wb[idx];
}

__global__ void k_pool(const float* __restrict__ h, const int* __restrict__ pred) {
    int b = blockIdx.x, j = threadIdx.x;
    float acc = 0.0f;
#pragma unroll 4
    for (int p = 0; p < PPG; p++) {
        int node = pred[b * PPG + p];
        acc += h[(size_t)node * HH + j];
    }
    g_pool[b * HH + j] = acc * (1.0f / PPG);
}

__global__ void k_tp() {
    int b = blockIdx.x, hrow = threadIdx.x;
    __shared__ float ps[HH];
    ps[hrow] = g_pool[b * HH + hrow];
    __syncthreads();
    float acc = 0.0f;
#pragma unroll 8
    for (int k = 0; k < HH; k++)
        acc += g_wbt[(size_t)k * HH + hrow] * ps[k];
    g_tp[b * HH + hrow] = acc;
}

__global__ void k_score(const float* __restrict__ h, const int* __restrict__ pred,
                        const float* __restrict__ bbp, float* __restrict__ out)
{
    int b = blockIdx.x;
    int tid = threadIdx.x;
    __shared__ __align__(16) float tps[HH];
    __shared__ float sc[PPG];
    tps[tid] = g_tp[b * HH + tid];
    __syncthreads();
    int warp = tid >> 5, lane = tid & 31;
    float4 tv = ((const float4*)tps)[lane];
    for (int p = warp; p < PPG; p += 4) {
        int node = pred[b * PPG + p];
        float4 hv = ((const float4*)h)[(size_t)node * 32 + lane];
        float d = hv.x * tv.x + hv.y * tv.y + hv.z * tv.z + hv.w * tv.w;
#pragma unroll
        for (int o = 16; o > 0; o >>= 1) d += __shfl_xor_sync(0xffffffffu, d, o);
        if (lane == 0) sc[p] = d + bbp[0];
    }
    __syncthreads();
    if (tid < 32) {
        float v = sc[tid];
        float m = v;
#pragma unroll
        for (int o = 16; o > 0; o >>= 1) m = fmaxf(m, __shfl_xor_sync(0xffffffffu, m, o));
        float e = expf(v - m);
        float s = e;
#pragma unroll
        for (int o = 16; o > 0; o >>= 1) s += __shfl_xor_sync(0xffffffffu, s, o);
        out[b * PPG + tid] = v - m - logf(s);
    }
}

// ---------------- launch ----------------
extern "C" void kernel_launch(void* const* d_in, const int* in_sizes, int n_in,
                              void* d_out, int out_size)
{
    (void)in_sizes; (void)n_in; (void)out_size;
    const float* emb_table = (const float*)d_in[0];
    const float* W_t       = (const float*)d_in[1];
    const float* b_t       = (const float*)d_in[2];
    const float* W_r       = (const float*)d_in[3];
    const float* b_r       = (const float*)d_in[4];
    const float* Wb        = (const float*)d_in[5];
    const float* bb        = (const float*)d_in[6];
    const float* norm      = (const float*)d_in[7];
    const int*   gid       = (const int*)d_in[8];
    const int*   spo       = (const int*)d_in[9];
    const int*   access_   = (const int*)d_in[10];
    const int*   pre       = (const int*)d_in[11];
    const int*   src       = (const int*)d_in[12];
    const int*   dst       = (const int*)d_in[13];
    const int*   etype     = (const int*)d_in[14];
    const int*   pred      = (const int*)d_in[15];
    float* out = (float*)d_out;

    void *p_cnt, *p_h, *p_h2, *p_mh, *p_ml, *p_wh, *p_wl;
    cudaGetSymbolAddress(&p_cnt, g_cnt);
    cudaGetSymbolAddress(&p_h,   g_h);
    cudaGetSymbolAddress(&p_h2,  g_h2);
    cudaGetSymbolAddress(&p_mh,  g_mh);
    cudaGetSymbolAddress(&p_ml,  g_ml);
    cudaGetSymbolAddress(&p_wh,  g_wh);
    cudaGetSymbolAddress(&p_wl,  g_wl);

    const int TPB = 256;
    const int node_warp_blocks = NN / 8;
    const int gemm_blocks      = NN / 128;
    const int proj_blocks      = VPAD / 128;

    cudaFuncSetAttribute(k_proj,   cudaFuncAttributeMaxDynamicSharedMemorySize, SM_TOT);
    cudaFuncSetAttribute(k_gemm_l, cudaFuncAttributeMaxDynamicSharedMemorySize, GL_TOT);

    // --- CSR build + weight split + table projection ---
    cudaMemsetAsync(p_cnt, 0, (size_t)NKEY * sizeof(int), 0);
    k_count<<<EE / TPB, TPB>>>(dst, etype);
    k_wsplit<<<(2 * 4 * HH * HH) / TPB, TPB>>>(W_r);
    k_proj<<<proj_blocks, TPB, SM_TOT>>>(emb_table, W_t);
    k_scan1<<<512, 256>>>();
    k_scan2<<<1, 512>>>();
    k_scan3<<<512, 256>>>();
    k_fill<<<EE / TPB, TPB>>>(src, dst, etype, norm);

    // --- init: h0 directly ---
    k_init2<<<node_warp_blocks, TPB>>>(gid, spo, access_, pre, W_t, b_t, (float*)p_h);

    // --- layer 0 ---
    k_gather4<<<node_warp_blocks, TPB>>>((const float*)p_h);
    k_gemm_l<<<gemm_blocks, TPB, GL_TOT>>>((const uint16_t*)p_mh, (const uint16_t*)p_ml,
                                           (const uint16_t*)p_wh, (const uint16_t*)p_wl,
                                           b_r, (const float*)p_h, (float*)p_h2);

    // --- layer 1 ---
    k_gather4<<<node_warp_blocks, TPB>>>((const float*)p_h2);
    k_gemm_l<<<gemm_blocks, TPB, GL_TOT>>>((const uint16_t*)p_mh, (const uint16_t*)p_ml,
                                           (const uint16_t*)p_wh + 4 * HH * HH,
                                           (const uint16_t*)p_wl + 4 * HH * HH,
                                           b_r + HH, nullptr, (float*)p_h);

    // --- head ---
    k_transpose<<<(HH * HH) / TPB, TPB>>>(Wb);
    k_pool<<<BBG, HH>>>((const float*)p_h, pred);
    k_tp<<<BBG, HH>>>();
    k_score<<<BBG, HH>>>((const float*)p_h, pred, bb, out);
}

// round 12
// speedup vs baseline: 1.0670x; 1.0670x over previous
#include <cuda_runtime.h>
#include <cuda_bf16.h>
#include <cstdint>

#define NN   131072
#define EE   1048576
#define HH   128
#define VV   30000
#define VPAD 30080     // 235 * 128
#define BBG  512
#define PPG  32
#define NH   (NN*HH)

// ---------------- static device scratch ----------------
__device__ float g_ptab[VPAD * HH];    // projected embedding table
__device__ float g_h[NH];
__device__ float g_h2[NH];
__device__ uint16_t g_mh[4ULL * NH];   // mailbox hi (bf16)
__device__ uint16_t g_ml[4ULL * NH];   // mailbox lo (bf16)
__device__ uint16_t g_wh[2 * 4 * HH * HH];  // W_r hi
__device__ uint16_t g_wl[2 * 4 * HH * HH];  // W_r lo
__device__ float g_pool[BBG * HH];
__device__ float g_tp[BBG * HH];
__device__ float g_wbt[HH * HH];
// dst-keyed CSR
__device__ int  g_cnt[NN];
__device__ int  g_off[NN + 1];
__device__ int  g_cur[NN];
__device__ int  g_bsum[128];
__device__ int2 g_rec[EE];             // {src | etype<<20, norm bits}

// ---------------- helpers ----------------
__device__ __forceinline__ uint32_t smem_u32(const void* p) {
    uint32_t a;
    asm("{ .reg .u64 t; cvta.to.shared.u64 t, %1; cvt.u32.u64 %0, t; }" : "=r"(a) : "l"(p));
    return a;
}
__device__ __forceinline__ void ldsm_x4(uint32_t r[4], uint32_t addr) {
    asm volatile("ldmatrix.sync.aligned.m8n8.x4.shared.b16 {%0,%1,%2,%3}, [%4];"
                 : "=r"(r[0]), "=r"(r[1]), "=r"(r[2]), "=r"(r[3]) : "r"(addr));
}
__device__ __forceinline__ void ldsm_x4_t(uint32_t r[4], uint32_t addr) {
    asm volatile("ldmatrix.sync.aligned.m8n8.x4.trans.shared.b16 {%0,%1,%2,%3}, [%4];"
                 : "=r"(r[0]), "=r"(r[1]), "=r"(r[2]), "=r"(r[3]) : "r"(addr));
}
__device__ __forceinline__ void mma_bf16(float* c, const uint32_t a[4], const uint32_t* b) {
    asm volatile(
        "mma.sync.aligned.m16n8k16.row.col.f32.bf16.bf16.f32 "
        "{%0,%1,%2,%3}, {%4,%5,%6,%7}, {%8,%9}, {%0,%1,%2,%3};"
        : "+f"(c[0]), "+f"(c[1]), "+f"(c[2]), "+f"(c[3])
        : "r"(a[0]), "r"(a[1]), "r"(a[2]), "r"(a[3]), "r"(b[0]), "r"(b[1]));
}
__device__ __forceinline__ void split2(float a, float b, uint32_t& hi, uint32_t& lo) {
    __nv_bfloat16 ha = __float2bfloat16_rn(a);
    __nv_bfloat16 hb = __float2bfloat16_rn(b);
    __nv_bfloat16 la = __float2bfloat16_rn(a - __bfloat162float(ha));
    __nv_bfloat16 lb = __float2bfloat16_rn(b - __bfloat162float(hb));
    hi = (uint32_t)__bfloat16_as_ushort(ha) | ((uint32_t)__bfloat16_as_ushort(hb) << 16);
    lo = (uint32_t)__bfloat16_as_ushort(la) | ((uint32_t)__bfloat16_as_ushort(lb) << 16);
}
__device__ __forceinline__ void cp16_ef(uint32_t smem, const void* g, uint64_t pol) {
    asm volatile("cp.async.cg.shared.global.L2::cache_hint [%0], [%1], 16, %2;"
                 :: "r"(smem), "l"(g), "l"(pol));
}
__device__ __forceinline__ void cp16(uint32_t smem, const void* g) {
    asm volatile("cp.async.cg.shared.global [%0], [%1], 16;" :: "r"(smem), "l"(g));
}

// ---------------- CSR build (dst-keyed) ----------------
__global__ void k_count(const int* __restrict__ dst) {
    int e = blockIdx.x * blockDim.x + threadIdx.x;
    if (e >= EE) return;
    atomicAdd(&g_cnt[dst[e]], 1);
}

__global__ void k_scan1() {
    __shared__ int s[256];
    int t = threadIdx.x;
    int4 v = *(const int4*)(g_cnt + blockIdx.x * 1024 + t * 4);
    s[t] = v.x + v.y + v.z + v.w;
    __syncthreads();
    for (int o = 128; o > 0; o >>= 1) {
        if (t < o) s[t] += s[t + o];
        __syncthreads();
    }
    if (t == 0) g_bsum[blockIdx.x] = s[0];
}

__global__ void k_scan2() {
    __shared__ int s[128];
    int t = threadIdx.x;
    int mine = g_bsum[t];
    s[t] = mine;
    __syncthreads();
    for (int o = 1; o < 128; o <<= 1) {
        int add = (t >= o) ? s[t - o] : 0;
        __syncthreads();
        s[t] += add;
        __syncthreads();
    }
    g_bsum[t] = s[t] - mine;
}

__global__ void k_scan3() {
    __shared__ int s[256];
    int t = threadIdx.x;
    int base = blockIdx.x * 1024 + t * 4;
    int4 v = *(const int4*)(g_cnt + base);
    int tsum = v.x + v.y + v.z + v.w;
    s[t] = tsum;
    __syncthreads();
    for (int o = 1; o < 256; o <<= 1) {
        int add = (t >= o) ? s[t - o] : 0;
        __syncthreads();
        s[t] += add;
        __syncthreads();
    }
    int o0 = s[t] - tsum + g_bsum[blockIdx.x];
    int o1 = o0 + v.x, o2 = o1 + v.y, o3 = o2 + v.z;
    *(int4*)(g_off + base) = make_int4(o0, o1, o2, o3);
    *(int4*)(g_cur + base) = make_int4(o0, o1, o2, o3);
    if (base + 4 == NN) g_off[NN] = o3 + v.w;
}

__global__ void k_fill(const int* __restrict__ src, const int* __restrict__ dst,
                       const int* __restrict__ et,  const float* __restrict__ norm) {
    int e = blockIdx.x * blockDim.x + threadIdx.x;
    if (e >= EE) return;
    int p = atomicAdd(&g_cur[dst[e]], 1);
    g_rec[p] = make_int2(src[e] | (et[e] << 20), __float_as_int(norm[e]));
}

// ---------------- weight split ----------------
__global__ void k_wsplit(const float* __restrict__ Wr) {
    int i = blockIdx.x * blockDim.x + threadIdx.x;
    float v = Wr[i];
    __nv_bfloat16 h = __float2bfloat16_rn(v);
    g_wh[i] = __bfloat16_as_ushort(h);
    g_wl[i] = __bfloat16_as_ushort(__float2bfloat16_rn(v - __bfloat162float(h)));
}

// ---------------- projected table: ptab = emb_table @ Wt[:128] ----------------
#define SM_AHI 0
#define SM_ALO 18432
#define SM_BHI 36864
#define SM_BLO 54272
#define SM_TOT 71680

__global__ void __launch_bounds__(256, 2) k_proj(
    const float* __restrict__ A, const float* __restrict__ Wt)
{
    extern __shared__ char smem[];
    uint32_t s0 = smem_u32(smem);
    int tid = threadIdx.x, wid = tid >> 5, lane = tid & 31;
    int row0 = blockIdx.x * 128;
    int warp_m = wid & 1, warp_n = wid >> 1;

    float c[4][4][4];
#pragma unroll
    for (int i = 0; i < 4; i++)
#pragma unroll
        for (int j = 0; j < 4; j++)
#pragma unroll
            for (int q = 0; q < 4; q++) c[i][j][q] = 0.0f;

    for (int ch = 0; ch < 2; ch++) {
        if (tid < 128) {
#pragma unroll
            for (int p = 0; p < 16; p++) {
                int e = p * 128 + tid;
                int r = e >> 4, c4 = e & 15;
                int rg = min(row0 + r, VV - 1);
                float4 v = *(const float4*)(A + (size_t)rg * HH + ch * 64 + c4 * 4);
                uint32_t h0, l0, h1, l1;
                split2(v.x, v.y, h0, l0);
                split2(v.z, v.w, h1, l1);
                uint32_t off = (uint32_t)r * 144 + c4 * 8;
                *(uint2*)(smem + SM_AHI + off) = make_uint2(h0, h1);
                *(uint2*)(smem + SM_ALO + off) = make_uint2(l0, l1);
            }
        } else {
            int t = tid - 128;
            const float* gb = Wt + (size_t)(ch * 64) * HH;
#pragma unroll
            for (int p = 0; p < 16; p++) {
                int e = p * 128 + t;
                int k = e >> 5, c4 = e & 31;
                float4 v = *(const float4*)(gb + (size_t)k * HH + c4 * 4);
                uint32_t h0, l0, h1, l1;
                split2(v.x, v.y, h0, l0);
                split2(v.z, v.w, h1, l1);
                uint32_t off = (uint32_t)k * 272 + c4 * 8;
                *(uint2*)(smem + SM_BHI + off) = make_uint2(h0, h1);
                *(uint2*)(smem + SM_BLO + off) = make_uint2(l0, l1);
            }
        }
        __syncthreads();

#pragma unroll
        for (int ks = 0; ks < 4; ks++) {
            uint32_t ah[4][4], al[4][4];
#pragma unroll
            for (int mt = 0; mt < 4; mt++) {
                uint32_t row  = warp_m * 64 + mt * 16 + (lane & 15);
                uint32_t addr = s0 + SM_AHI + row * 144 + ks * 32 + ((lane >> 4) << 4);
                ldsm_x4(ah[mt], addr);
                ldsm_x4(al[mt], addr + (SM_ALO - SM_AHI));
            }
#pragma unroll
            for (int np = 0; np < 2; np++) {
                uint32_t kk   = ks * 16 + (lane & 15);
                uint32_t col  = warp_n * 32 + np * 16 + ((lane >> 4) & 1) * 8;
                uint32_t addr = s0 + SM_BHI + kk * 272 + col * 2;
                uint32_t bh[4], bl[4];
                ldsm_x4_t(bh, addr);
                ldsm_x4_t(bl, addr + (SM_BLO - SM_BHI));
#pragma unroll
                for (int mt = 0; mt < 4; mt++) {
                    mma_bf16(c[mt][np * 2],     ah[mt], bh);
                    mma_bf16(c[mt][np * 2],     al[mt], bh);
                    mma_bf16(c[mt][np * 2],     ah[mt], bl);
                    mma_bf16(c[mt][np * 2 + 1], ah[mt], bh + 2);
                    mma_bf16(c[mt][np * 2 + 1], al[mt], bh + 2);
                    mma_bf16(c[mt][np * 2 + 1], ah[mt], bl + 2);
                }
            }
        }
        __syncthreads();
    }

#pragma unroll
    for (int mt = 0; mt < 4; mt++) {
#pragma unroll
        for (int nt = 0; nt < 4; nt++) {
            int col = warp_n * 32 + nt * 8 + (lane & 3) * 2;
#pragma unroll
            for (int half = 0; half < 2; half++) {
                long row = row0 + warp_m * 64 + mt * 16 + (lane >> 2) + half * 8;
                if (row < VV)
                    *(float2*)(g_ptab + row * HH + col) =
                        make_float2(c[mt][nt][half * 2 + 0], c[mt][nt][half * 2 + 1]);
            }
        }
    }
}

// ---------------- init: h0 directly from ptab (warp per node, CSR) ----------------
__global__ void k_init2(const int* __restrict__ gid, const int* __restrict__ spo,
                        const int* __restrict__ acc_, const int* __restrict__ pre,
                        const float* __restrict__ Wt, const float* __restrict__ bt,
                        float* __restrict__ hout)
{
    __shared__ float sw[768];
    for (int i = threadIdx.x; i < 768; i += blockDim.x)
        sw[i] = (i < 640) ? Wt[(size_t)(128 + (i >> 7)) * HH + (i & 127)] : bt[i - 640];
    __syncthreads();

    int node = (blockIdx.x * blockDim.x + threadIdx.x) >> 5;
    int lane = threadIdx.x & 31;
    if (node >= NN) return;
    int s0 = spo[node * 3 + 0];
    int s1 = spo[node * 3 + 1];
    int s2 = spo[node * 3 + 2];
    int beg = g_off[node], end = g_off[node + 1];

    float4 a = make_float4(0.f, 0.f, 0.f, 0.f);
    bool has_ne = false;
    for (int base = beg; base < end; base += 32) {
        int n = min(32, end - base);
        int2 r = (base + lane < end) ? __ldcs(&g_rec[base + lane]) : make_int2(-1, 0);
        for (int i = 0; i < n; i++) {
            int rx = __shfl_sync(0xffffffffu, r.x, i);
            int rn = __shfl_sync(0xffffffffu, r.y, i);
            if ((rx >> 20) != 0) continue;
            has_ne = true;
            int s = rx & 0xFFFFF;
            float nw = __int_as_float(rn);
            float4 hv = ((const float4*)g_ptab)[(size_t)gid[s] * 32 + lane];
            a.x += hv.x * nw; a.y += hv.y * nw;
            a.z += hv.z * nw; a.w += hv.w * nw;
        }
    }
    float4 e4;
    if ((s0 + s2) > 0 && has_ne) e4 = a;
    else                         e4 = ((const float4*)g_ptab)[(size_t)gid[node] * 32 + lane];

    float cf0 = (float)s0, cf1 = (float)s1, cf2 = (float)s2;
    float cf3 = (float)acc_[node], cf4 = (float)pre[node];
    int col = lane * 4;
#pragma unroll
    for (int q = 0; q < 4; q++) {
        float add = sw[640 + col + q]
                  + cf0 * sw[col + q]       + cf1 * sw[128 + col + q]
                  + cf2 * sw[256 + col + q] + cf3 * sw[384 + col + q]
                  + cf4 * sw[512 + col + q];
        (&e4.x)[q] += add;
    }
    ((float4*)hout)[(size_t)node * 32 + lane] = e4;
}

// ---------------- gather-first: one CSR pass, streaming mailbox writes ------
__global__ void k_gather4(const float* __restrict__ h)
{
    int node = (blockIdx.x * blockDim.x + threadIdx.x) >> 5;
    int lane = threadIdx.x & 31;
    if (node >= NN) return;
    int beg = g_off[node], end = g_off[node + 1];

    float4 a0 = make_float4(0.f, 0.f, 0.f, 0.f);
    float4 a1 = a0, a2 = a0, a3 = a0;
    for (int base = beg; base < end; base += 32) {
        int n = min(32, end - base);
        int2 r = (base + lane < end) ? __ldcs(&g_rec[base + lane]) : make_int2(0, 0);
        for (int i = 0; i < n; i++) {
            int rx = __shfl_sync(0xffffffffu, r.x, i);
            int rn = __shfl_sync(0xffffffffu, r.y, i);
            int s = rx & 0xFFFFF;
            int t = rx >> 20;
            float nw = __int_as_float(rn);
            float4 v = *(const float4*)(h + (size_t)s * HH + lane * 4);
            switch (t) {
            case 0: a0.x += v.x*nw; a0.y += v.y*nw; a0.z += v.z*nw; a0.w += v.w*nw; break;
            case 1: a1.x += v.x*nw; a1.y += v.y*nw; a1.z += v.z*nw; a1.w += v.w*nw; break;
            case 2: a2.x += v.x*nw; a2.y += v.y*nw; a2.z += v.z*nw; a2.w += v.w*nw; break;
            default:a3.x += v.x*nw; a3.y += v.y*nw; a3.z += v.z*nw; a3.w += v.w*nw; break;
            }
        }
    }
    size_t o = (size_t)node * 32 + lane;
    float4 acc[4] = {a0, a1, a2, a3};
#pragma unroll
    for (int t = 0; t < 4; t++) {
        uint32_t h0, l0, h1, l1;
        split2(acc[t].x, acc[t].y, h0, l0);
        split2(acc[t].z, acc[t].w, h1, l1);
        unsigned long long ph = (unsigned long long)h0 | ((unsigned long long)h1 << 32);
        unsigned long long pl = (unsigned long long)l0 | ((unsigned long long)l1 << 32);
        __stcs((unsigned long long*)(g_mh + (size_t)t * NH) + o, ph);
        __stcs((unsigned long long*)(g_ml + (size_t)t * NH) + o, pl);
    }
}

// ---------------- layer GEMM: cp.async double-buffered, evict-first A ----------
#define GL_AHI 0
#define GL_ALO 10240
#define GL_BHI 20480
#define GL_BLO 29184
#define GL_BUF 37888
#define GL_TOT 75776

__global__ void __launch_bounds__(256, 2) k_gemm_l(
    const uint16_t* __restrict__ mh, const uint16_t* __restrict__ ml,
    const uint16_t* __restrict__ wh, const uint16_t* __restrict__ wl,
    const float* __restrict__ bias, const float* __restrict__ resid,
    float* __restrict__ C)
{
    extern __shared__ char smem[];
    uint32_t s0 = smem_u32(smem);
    int tid = threadIdx.x, wid = tid >> 5, lane = tid & 31;
    int row0 = blockIdx.x * 128;
    int warp_m = wid & 1, warp_n = wid >> 1;

    uint64_t pol;
    asm("createpolicy.fractional.L2::evict_first.b64 %0, 1.0;" : "=l"(pol));

    float c[4][4][4];
#pragma unroll
    for (int i = 0; i < 4; i++)
#pragma unroll
        for (int j = 0; j < 4; j++)
#pragma unroll
            for (int q = 0; q < 4; q++) c[i][j][q] = 0.0f;

    auto load_chunk = [&](int ch, int buf) {
        int t = ch >> 2, sub = ch & 3;
        const uint16_t* mhb = mh + (size_t)t * NH + (size_t)row0 * HH + sub * 32;
        const uint16_t* mlb = ml + (size_t)t * NH + (size_t)row0 * HH + sub * 32;
        const uint16_t* whb = wh + (size_t)t * HH * HH + (size_t)(sub * 32) * HH;
        const uint16_t* wlb = wl + (size_t)t * HH * HH + (size_t)(sub * 32) * HH;
        uint32_t sb = s0 + buf * GL_BUF;
#pragma unroll
        for (int q = 0; q < 2; q++) {
            int s = q * 256 + tid;
            int r = s >> 2, part = s & 3;
            cp16_ef(sb + GL_AHI + r * 80 + part * 16, mhb + (size_t)r * HH + part * 8, pol);
            cp16_ef(sb + GL_ALO + r * 80 + part * 16, mlb + (size_t)r * HH + part * 8, pol);
        }
#pragma unroll
        for (int q = 0; q < 2; q++) {
            int s = q * 256 + tid;
            int r = s >> 4, part = s & 15;
            cp16(sb + GL_BHI + r * 272 + part * 16, whb + (size_t)r * HH + part * 8);
            cp16(sb + GL_BLO + r * 272 + part * 16, wlb + (size_t)r * HH + part * 8);
        }
    };

    load_chunk(0, 0);
    asm volatile("cp.async.commit_group;" ::: "memory");

    for (int ch = 0; ch < 16; ch++) {
        if (ch + 1 < 16) {
            load_chunk(ch + 1, (ch + 1) & 1);
            asm volatile("cp.async.commit_group;" ::: "memory");
            asm volatile("cp.async.wait_group 1;" ::: "memory");
        } else {
            asm volatile("cp.async.wait_group 0;" ::: "memory");
        }
        __syncthreads();

        uint32_t sb = s0 + (ch & 1) * GL_BUF;
#pragma unroll
        for (int ks = 0; ks < 2; ks++) {
            uint32_t ah[4][4], al[4][4];
#pragma unroll
            for (int mt = 0; mt < 4; mt++) {
                uint32_t row  = warp_m * 64 + mt * 16 + (lane & 15);
                uint32_t addr = sb + GL_AHI + row * 80 + ks * 32 + ((lane >> 4) << 4);
                ldsm_x4(ah[mt], addr);
                ldsm_x4(al[mt], addr + (GL_ALO - GL_AHI));
            }
#pragma unroll
            for (int np = 0; np < 2; np++) {
                uint32_t kk   = ks * 16 + (lane & 15);
                uint32_t col  = warp_n * 32 + np * 16 + ((lane >> 4) & 1) * 8;
                uint32_t addr = sb + GL_BHI + kk * 272 + col * 2;
                uint32_t bh[4], bl[4];
                ldsm_x4_t(bh, addr);
                ldsm_x4_t(bl, addr + (GL_BLO - GL_BHI));
#pragma unroll
                for (int mt = 0; mt < 4; mt++) {
                    mma_bf16(c[mt][np * 2],     ah[mt], bh);
                    mma_bf16(c[mt][np * 2],     al[mt], bh);
                    mma_bf16(c[mt][np * 2],     ah[mt], bl);
                    mma_bf16(c[mt][np * 2 + 1], ah[mt], bh + 2);
                    mma_bf16(c[mt][np * 2 + 1], al[mt], bh + 2);
                    mma_bf16(c[mt][np * 2 + 1], ah[mt], bl + 2);
                }
            }
        }
        __syncthreads();
    }

#pragma unroll
    for (int mt = 0; mt < 4; mt++) {
#pragma unroll
        for (int nt = 0; nt < 4; nt++) {
            int col = warp_n * 32 + nt * 8 + (lane & 3) * 2;
            float2 bv = *(const float2*)(bias + col);
#pragma unroll
            for (int half = 0; half < 2; half++) {
                long row  = row0 + warp_m * 64 + mt * 16 + (lane >> 2) + half * 8;
                long base = row * HH + col;
                float2 v;
                v.x = fmaxf(c[mt][nt][half * 2 + 0] + bv.x, 0.f);
                v.y = fmaxf(c[mt][nt][half * 2 + 1] + bv.y, 0.f);
                if (resid) {
                    float2 rr = __ldcs((const float2*)(resid + base));
                    v.x += rr.x; v.y += rr.y;
                }
                *(float2*)(C + base) = v;
            }
        }
    }
}

// ---------------- head kernels ----------------
__global__ void k_transpose(const float* __restrict__ Wb) {
    int idx = blockIdx.x * blockDim.x + threadIdx.x;
    if (idx >= HH * HH) return;
    int r = idx >> 7, c = idx & 127;
    g_wbt[c * HH + r] = Wb[idx];
}

__global__ void k_pool(const float* __restrict__ h, const int* __restrict__ pred) {
    int b = blockIdx.x, j = threadIdx.x;
    float acc = 0.0f;
#pragma unroll 4
    for (int p = 0; p < PPG; p++) {
        int node = pred[b * PPG + p];
        acc += h[(size_t)node * HH + j];
    }
    g_pool[b * HH + j] = acc * (1.0f / PPG);
}

__global__ void k_tp() {
    int b = blockIdx.x, hrow = threadIdx.x;
    __shared__ float ps[HH];
    ps[hrow] = g_pool[b * HH + hrow];
    __syncthreads();
    float acc = 0.0f;
#pragma unroll 8
    for (int k = 0; k < HH; k++)
        acc += g_wbt[(size_t)k * HH + hrow] * ps[k];
    g_tp[b * HH + hrow] = acc;
}

__global__ void k_score(const float* __restrict__ h, const int* __restrict__ pred,
                        const float* __restrict__ bbp, float* __restrict__ out)
{
    int b = blockIdx.x;
    int tid = threadIdx.x;
    __shared__ __align__(16) float tps[HH];
    __shared__ float sc[PPG];
    tps[tid] = g_tp[b * HH + tid];
    __syncthreads();
    int warp = tid >> 5, lane = tid & 31;
    float4 tv = ((const float4*)tps)[lane];
    for (int p = warp; p < PPG; p += 4) {
        int node = pred[b * PPG + p];
        float4 hv = ((const float4*)h)[(size_t)node * 32 + lane];
        float d = hv.x * tv.x + hv.y * tv.y + hv.z * tv.z + hv.w * tv.w;
#pragma unroll
        for (int o = 16; o > 0; o >>= 1) d += __shfl_xor_sync(0xffffffffu, d, o);
        if (lane == 0) sc[p] = d + bbp[0];
    }
    __syncthreads();
    if (tid < 32) {
        float v = sc[tid];
        float m = v;
#pragma unroll
        for (int o = 16; o > 0; o >>= 1) m = fmaxf(m, __shfl_xor_sync(0xffffffffu, m, o));
        float e = expf(v - m);
        float s = e;
#pragma unroll
        for (int o = 16; o > 0; o >>= 1) s += __shfl_xor_sync(0xffffffffu, s, o);
        out[b * PPG + tid] = v - m - logf(s);
    }
}

// ---------------- launch ----------------
extern "C" void kernel_launch(void* const* d_in, const int* in_sizes, int n_in,
                              void* d_out, int out_size)
{
    (void)in_sizes; (void)n_in; (void)out_size;
    const float* emb_table = (const float*)d_in[0];
    const float* W_t       = (const float*)d_in[1];
    const float* b_t       = (const float*)d_in[2];
    const float* W_r       = (const float*)d_in[3];
    const float* b_r       = (const float*)d_in[4];
    const float* Wb        = (const float*)d_in[5];
    const float* bb        = (const float*)d_in[6];
    const float* norm      = (const float*)d_in[7];
    const int*   gid       = (const int*)d_in[8];
    const int*   spo       = (const int*)d_in[9];
    const int*   access_   = (const int*)d_in[10];
    const int*   pre       = (const int*)d_in[11];
    const int*   src       = (const int*)d_in[12];
    const int*   dst       = (const int*)d_in[13];
    const int*   etype     = (const int*)d_in[14];
    const int*   pred      = (const int*)d_in[15];
    float* out = (float*)d_out;

    void *p_cnt, *p_h, *p_h2, *p_mh, *p_ml, *p_wh, *p_wl;
    cudaGetSymbolAddress(&p_cnt, g_cnt);
    cudaGetSymbolAddress(&p_h,   g_h);
    cudaGetSymbolAddress(&p_h2,  g_h2);
    cudaGetSymbolAddress(&p_mh,  g_mh);
    cudaGetSymbolAddress(&p_ml,  g_ml);
    cudaGetSymbolAddress(&p_wh,  g_wh);
    cudaGetSymbolAddress(&p_wl,  g_wl);

    const int TPB = 256;
    const int node_warp_blocks = NN / 8;
    const int gemm_blocks      = NN / 128;
    const int proj_blocks      = VPAD / 128;

    cudaFuncSetAttribute(k_proj,   cudaFuncAttributeMaxDynamicSharedMemorySize, SM_TOT);
    cudaFuncSetAttribute(k_gemm_l, cudaFuncAttributeMaxDynamicSharedMemorySize, GL_TOT);

    // --- CSR build + weight split + table projection ---
    cudaMemsetAsync(p_cnt, 0, (size_t)NN * sizeof(int), 0);
    k_count<<<EE / TPB, TPB>>>(dst);
    k_wsplit<<<(2 * 4 * HH * HH) / TPB, TPB>>>(W_r);
    k_proj<<<proj_blocks, TPB, SM_TOT>>>(emb_table, W_t);
    k_scan1<<<128, 256>>>();
    k_scan2<<<1, 128>>>();
    k_scan3<<<128, 256>>>();
    k_fill<<<EE / TPB, TPB>>>(src, dst, etype, norm);

    // --- init: h0 directly ---
    k_init2<<<node_warp_blocks, TPB>>>(gid, spo, access_, pre, W_t, b_t, (float*)p_h);

    // --- layer 0 ---
    k_gather4<<<node_warp_blocks, TPB>>>((const float*)p_h);
    k_gemm_l<<<gemm_blocks, TPB, GL_TOT>>>((const uint16_t*)p_mh, (const uint16_t*)p_ml,
                                           (const uint16_t*)p_wh, (const uint16_t*)p_wl,
                                           b_r, (const float*)p_h, (float*)p_h2);

    // --- layer 1 ---
    k_gather4<<<node_warp_blocks, TPB>>>((const float*)p_h2);
    k_gemm_l<<<gemm_blocks, TPB, GL_TOT>>>((const uint16_t*)p_mh, (const uint16_t*)p_ml,
                                           (const uint16_t*)p_wh + 4 * HH * HH,
                                           (const uint16_t*)p_wl + 4 * HH * HH,
                                           b_r + HH, nullptr, (float*)p_h);

    // --- head ---
    k_transpose<<<(HH * HH) / TPB, TPB>>>(Wb);
    k_pool<<<BBG, HH>>>((const float*)p_h, pred);
    k_tp<<<BBG, HH>>>();
    k_score<<<BBG, HH>>>((const float*)p_h, pred, bb, out);
}

// round 13
// speedup vs baseline: 1.0999x; 1.0309x over previous
#include <cuda_runtime.h>
#include <cuda_bf16.h>
#include <cstdint>

#define NN   131072
#define EE   1048576
#define HH   128
#define VV   30000
#define VPAD 30080     // 235 * 128
#define BBG  512
#define PPG  32
#define NH   (NN*HH)

// ---------------- static device scratch ----------------
__device__ float g_ptab[VPAD * HH];    // projected embedding table
__device__ float g_h[NH];
__device__ float g_h2[NH];
__device__ uint16_t g_hb[NH];          // bf16 mirror of current h (gather reads)
__device__ uint16_t g_mh[4ULL * NH];   // mailbox hi (bf16)
__device__ uint16_t g_ml[4ULL * NH];   // mailbox lo (bf16)
__device__ uint16_t g_wh[2 * 4 * HH * HH];  // W_r hi
__device__ uint16_t g_wl[2 * 4 * HH * HH];  // W_r lo
__device__ float g_pool[BBG * HH];
__device__ float g_tp[BBG * HH];
__device__ float g_wbt[HH * HH];
// dst-keyed CSR
__device__ int  g_cnt[NN];
__device__ int  g_off[NN + 1];
__device__ int  g_cur[NN];
__device__ int  g_bsum[128];
__device__ int2 g_rec[EE];             // {src | etype<<20, norm bits}

// ---------------- helpers ----------------
__device__ __forceinline__ uint32_t smem_u32(const void* p) {
    uint32_t a;
    asm("{ .reg .u64 t; cvta.to.shared.u64 t, %1; cvt.u32.u64 %0, t; }" : "=r"(a) : "l"(p));
    return a;
}
__device__ __forceinline__ void ldsm_x4(uint32_t r[4], uint32_t addr) {
    asm volatile("ldmatrix.sync.aligned.m8n8.x4.shared.b16 {%0,%1,%2,%3}, [%4];"
                 : "=r"(r[0]), "=r"(r[1]), "=r"(r[2]), "=r"(r[3]) : "r"(addr));
}
__device__ __forceinline__ void ldsm_x4_t(uint32_t r[4], uint32_t addr) {
    asm volatile("ldmatrix.sync.aligned.m8n8.x4.trans.shared.b16 {%0,%1,%2,%3}, [%4];"
                 : "=r"(r[0]), "=r"(r[1]), "=r"(r[2]), "=r"(r[3]) : "r"(addr));
}
__device__ __forceinline__ void mma_bf16(float* c, const uint32_t a[4], const uint32_t* b) {
    asm volatile(
        "mma.sync.aligned.m16n8k16.row.col.f32.bf16.bf16.f32 "
        "{%0,%1,%2,%3}, {%4,%5,%6,%7}, {%8,%9}, {%0,%1,%2,%3};"
        : "+f"(c[0]), "+f"(c[1]), "+f"(c[2]), "+f"(c[3])
        : "r"(a[0]), "r"(a[1]), "r"(a[2]), "r"(a[3]), "r"(b[0]), "r"(b[1]));
}
__device__ __forceinline__ void split2(float a, float b, uint32_t& hi, uint32_t& lo) {
    __nv_bfloat16 ha = __float2bfloat16_rn(a);
    __nv_bfloat16 hb = __float2bfloat16_rn(b);
    __nv_bfloat16 la = __float2bfloat16_rn(a - __bfloat162float(ha));
    __nv_bfloat16 lb = __float2bfloat16_rn(b - __bfloat162float(hb));
    hi = (uint32_t)__bfloat16_as_ushort(ha) | ((uint32_t)__bfloat16_as_ushort(hb) << 16);
    lo = (uint32_t)__bfloat16_as_ushort(la) | ((uint32_t)__bfloat16_as_ushort(lb) << 16);
}
__device__ __forceinline__ uint32_t pack_bf16(float a, float b) {
    __nv_bfloat162 p = __floats2bfloat162_rn(a, b);
    return *reinterpret_cast<uint32_t*>(&p);
}
__device__ __forceinline__ void cp16_ef(uint32_t smem, const void* g, uint64_t pol) {
    asm volatile("cp.async.cg.shared.global.L2::cache_hint [%0], [%1], 16, %2;"
                 :: "r"(smem), "l"(g), "l"(pol));
}
__device__ __forceinline__ void cp16(uint32_t smem, const void* g) {
    asm volatile("cp.async.cg.shared.global [%0], [%1], 16;" :: "r"(smem), "l"(g));
}

// ---------------- CSR build (dst-keyed) ----------------
__global__ void k_count(const int* __restrict__ dst) {
    int e = blockIdx.x * blockDim.x + threadIdx.x;
    if (e >= EE) return;
    atomicAdd(&g_cnt[dst[e]], 1);
}

__global__ void k_scan1() {
    __shared__ int s[256];
    int t = threadIdx.x;
    int4 v = *(const int4*)(g_cnt + blockIdx.x * 1024 + t * 4);
    s[t] = v.x + v.y + v.z + v.w;
    __syncthreads();
    for (int o = 128; o > 0; o >>= 1) {
        if (t < o) s[t] += s[t + o];
        __syncthreads();
    }
    if (t == 0) g_bsum[blockIdx.x] = s[0];
}

__global__ void k_scan2() {
    __shared__ int s[128];
    int t = threadIdx.x;
    int mine = g_bsum[t];
    s[t] = mine;
    __syncthreads();
    for (int o = 1; o < 128; o <<= 1) {
        int add = (t >= o) ? s[t - o] : 0;
        __syncthreads();
        s[t] += add;
        __syncthreads();
    }
    g_bsum[t] = s[t] - mine;
}

__global__ void k_scan3() {
    __shared__ int s[256];
    int t = threadIdx.x;
    int base = blockIdx.x * 1024 + t * 4;
    int4 v = *(const int4*)(g_cnt + base);
    int tsum = v.x + v.y + v.z + v.w;
    s[t] = tsum;
    __syncthreads();
    for (int o = 1; o < 256; o <<= 1) {
        int add = (t >= o) ? s[t - o] : 0;
        __syncthreads();
        s[t] += add;
        __syncthreads();
    }
    int o0 = s[t] - tsum + g_bsum[blockIdx.x];
    int o1 = o0 + v.x, o2 = o1 + v.y, o3 = o2 + v.z;
    *(int4*)(g_off + base) = make_int4(o0, o1, o2, o3);
    *(int4*)(g_cur + base) = make_int4(o0, o1, o2, o3);
    if (base + 4 == NN) g_off[NN] = o3 + v.w;
}

__global__ void k_fill(const int* __restrict__ src, const int* __restrict__ dst,
                       const int* __restrict__ et,  const float* __restrict__ norm) {
    int e = blockIdx.x * blockDim.x + threadIdx.x;
    if (e >= EE) return;
    int p = atomicAdd(&g_cur[dst[e]], 1);
    g_rec[p] = make_int2(src[e] | (et[e] << 20), __float_as_int(norm[e]));
}

// ---------------- weight split ----------------
__global__ void k_wsplit(const float* __restrict__ Wr) {
    int i = blockIdx.x * blockDim.x + threadIdx.x;
    float v = Wr[i];
    __nv_bfloat16 h = __float2bfloat16_rn(v);
    g_wh[i] = __bfloat16_as_ushort(h);
    g_wl[i] = __bfloat16_as_ushort(__float2bfloat16_rn(v - __bfloat162float(h)));
}

// ---------------- projected table: ptab = emb_table @ Wt[:128] ----------------
#define SM_AHI 0
#define SM_ALO 18432
#define SM_BHI 36864
#define SM_BLO 54272
#define SM_TOT 71680

__global__ void __launch_bounds__(256, 2) k_proj(
    const float* __restrict__ A, const float* __restrict__ Wt)
{
    extern __shared__ char smem[];
    uint32_t s0 = smem_u32(smem);
    int tid = threadIdx.x, wid = tid >> 5, lane = tid & 31;
    int row0 = blockIdx.x * 128;
    int warp_m = wid & 1, warp_n = wid >> 1;

    float c[4][4][4];
#pragma unroll
    for (int i = 0; i < 4; i++)
#pragma unroll
        for (int j = 0; j < 4; j++)
#pragma unroll
            for (int q = 0; q < 4; q++) c[i][j][q] = 0.0f;

    for (int ch = 0; ch < 2; ch++) {
        if (tid < 128) {
#pragma unroll
            for (int p = 0; p < 16; p++) {
                int e = p * 128 + tid;
                int r = e >> 4, c4 = e & 15;
                int rg = min(row0 + r, VV - 1);
                float4 v = *(const float4*)(A + (size_t)rg * HH + ch * 64 + c4 * 4);
                uint32_t h0, l0, h1, l1;
                split2(v.x, v.y, h0, l0);
                split2(v.z, v.w, h1, l1);
                uint32_t off = (uint32_t)r * 144 + c4 * 8;
                *(uint2*)(smem + SM_AHI + off) = make_uint2(h0, h1);
                *(uint2*)(smem + SM_ALO + off) = make_uint2(l0, l1);
            }
        } else {
            int t = tid - 128;
            const float* gb = Wt + (size_t)(ch * 64) * HH;
#pragma unroll
            for (int p = 0; p < 16; p++) {
                int e = p * 128 + t;
                int k = e >> 5, c4 = e & 31;
                float4 v = *(const float4*)(gb + (size_t)k * HH + c4 * 4);
                uint32_t h0, l0, h1, l1;
                split2(v.x, v.y, h0, l0);
                split2(v.z, v.w, h1, l1);
                uint32_t off = (uint32_t)k * 272 + c4 * 8;
                *(uint2*)(smem + SM_BHI + off) = make_uint2(h0, h1);
                *(uint2*)(smem + SM_BLO + off) = make_uint2(l0, l1);
            }
        }
        __syncthreads();

#pragma unroll
        for (int ks = 0; ks < 4; ks++) {
            uint32_t ah[4][4], al[4][4];
#pragma unroll
            for (int mt = 0; mt < 4; mt++) {
                uint32_t row  = warp_m * 64 + mt * 16 + (lane & 15);
                uint32_t addr = s0 + SM_AHI + row * 144 + ks * 32 + ((lane >> 4) << 4);
                ldsm_x4(ah[mt], addr);
                ldsm_x4(al[mt], addr + (SM_ALO - SM_AHI));
            }
#pragma unroll
            for (int np = 0; np < 2; np++) {
                uint32_t kk   = ks * 16 + (lane & 15);
                uint32_t col  = warp_n * 32 + np * 16 + ((lane >> 4) & 1) * 8;
                uint32_t addr = s0 + SM_BHI + kk * 272 + col * 2;
                uint32_t bh[4], bl[4];
                ldsm_x4_t(bh, addr);
                ldsm_x4_t(bl, addr + (SM_BLO - SM_BHI));
#pragma unroll
                for (int mt = 0; mt < 4; mt++) {
                    mma_bf16(c[mt][np * 2],     ah[mt], bh);
                    mma_bf16(c[mt][np * 2],     al[mt], bh);
                    mma_bf16(c[mt][np * 2],     ah[mt], bl);
                    mma_bf16(c[mt][np * 2 + 1], ah[mt], bh + 2);
                    mma_bf16(c[mt][np * 2 + 1], al[mt], bh + 2);
                    mma_bf16(c[mt][np * 2 + 1], ah[mt], bl + 2);
                }
            }
        }
        __syncthreads();
    }

#pragma unroll
    for (int mt = 0; mt < 4; mt++) {
#pragma unroll
        for (int nt = 0; nt < 4; nt++) {
            int col = warp_n * 32 + nt * 8 + (lane & 3) * 2;
#pragma unroll
            for (int half = 0; half < 2; half++) {
                long row = row0 + warp_m * 64 + mt * 16 + (lane >> 2) + half * 8;
                if (row < VV)
                    *(float2*)(g_ptab + row * HH + col) =
                        make_float2(c[mt][nt][half * 2 + 0], c[mt][nt][half * 2 + 1]);
            }
        }
    }
}

// ---------------- init: h0 (fp32 + bf16 mirror) from ptab ----------------
__global__ void k_init2(const int* __restrict__ gid, const int* __restrict__ spo,
                        const int* __restrict__ acc_, const int* __restrict__ pre,
                        const float* __restrict__ Wt, const float* __restrict__ bt,
                        float* __restrict__ hout)
{
    __shared__ float sw[768];
    for (int i = threadIdx.x; i < 768; i += blockDim.x)
        sw[i] = (i < 640) ? Wt[(size_t)(128 + (i >> 7)) * HH + (i & 127)] : bt[i - 640];
    __syncthreads();

    int node = (blockIdx.x * blockDim.x + threadIdx.x) >> 5;
    int lane = threadIdx.x & 31;
    if (node >= NN) return;
    int s0 = spo[node * 3 + 0];
    int s1 = spo[node * 3 + 1];
    int s2 = spo[node * 3 + 2];
    int beg = g_off[node], end = g_off[node + 1];

    float4 a = make_float4(0.f, 0.f, 0.f, 0.f);
    bool has_ne = false;
    for (int base = beg; base < end; base += 32) {
        int n = min(32, end - base);
        int2 r = (base + lane < end) ? __ldcs(&g_rec[base + lane]) : make_int2(-1, 0);
        for (int i = 0; i < n; i++) {
            int rx = __shfl_sync(0xffffffffu, r.x, i);
            int rn = __shfl_sync(0xffffffffu, r.y, i);
            if ((rx >> 20) != 0) continue;
            has_ne = true;
            int s = rx & 0xFFFFF;
            float nw = __int_as_float(rn);
            float4 hv = ((const float4*)g_ptab)[(size_t)gid[s] * 32 + lane];
            a.x += hv.x * nw; a.y += hv.y * nw;
            a.z += hv.z * nw; a.w += hv.w * nw;
        }
    }
    float4 e4;
    if ((s0 + s2) > 0 && has_ne) e4 = a;
    else                         e4 = ((const float4*)g_ptab)[(size_t)gid[node] * 32 + lane];

    float cf0 = (float)s0, cf1 = (float)s1, cf2 = (float)s2;
    float cf3 = (float)acc_[node], cf4 = (float)pre[node];
    int col = lane * 4;
#pragma unroll
    for (int q = 0; q < 4; q++) {
        float add = sw[640 + col + q]
                  + cf0 * sw[col + q]       + cf1 * sw[128 + col + q]
                  + cf2 * sw[256 + col + q] + cf3 * sw[384 + col + q]
                  + cf4 * sw[512 + col + q];
        (&e4.x)[q] += add;
    }
    size_t o = (size_t)node * 32 + lane;
    ((float4*)hout)[o] = e4;
    ((uint2*)g_hb)[o] = make_uint2(pack_bf16(e4.x, e4.y), pack_bf16(e4.z, e4.w));
}

// ---------------- gather-first: bf16 h reads, one CSR pass --------------------
__global__ void k_gather4()
{
    int node = (blockIdx.x * blockDim.x + threadIdx.x) >> 5;
    int lane = threadIdx.x & 31;
    if (node >= NN) return;
    int beg = g_off[node], end = g_off[node + 1];

    float4 a0 = make_float4(0.f, 0.f, 0.f, 0.f);
    float4 a1 = a0, a2 = a0, a3 = a0;
    for (int base = beg; base < end; base += 32) {
        int n = min(32, end - base);
        int2 r = (base + lane < end) ? __ldcs(&g_rec[base + lane]) : make_int2(0, 0);
        for (int i = 0; i < n; i++) {
            int rx = __shfl_sync(0xffffffffu, r.x, i);
            int rn = __shfl_sync(0xffffffffu, r.y, i);
            int s = rx & 0xFFFFF;
            int t = rx >> 20;
            float nw = __int_as_float(rn);
            uint2 pv = ((const uint2*)g_hb)[(size_t)s * 32 + lane];
            float2 f0 = __bfloat1622float2(*reinterpret_cast<__nv_bfloat162*>(&pv.x));
            float2 f1 = __bfloat1622float2(*reinterpret_cast<__nv_bfloat162*>(&pv.y));
            switch (t) {
            case 0: a0.x += f0.x*nw; a0.y += f0.y*nw; a0.z += f1.x*nw; a0.w += f1.y*nw; break;
            case 1: a1.x += f0.x*nw; a1.y += f0.y*nw; a1.z += f1.x*nw; a1.w += f1.y*nw; break;
            case 2: a2.x += f0.x*nw; a2.y += f0.y*nw; a2.z += f1.x*nw; a2.w += f1.y*nw; break;
            default:a3.x += f0.x*nw; a3.y += f0.y*nw; a3.z += f1.x*nw; a3.w += f1.y*nw; break;
            }
        }
    }
    size_t o = (size_t)node * 32 + lane;
    float4 acc[4] = {a0, a1, a2, a3};
#pragma unroll
    for (int t = 0; t < 4; t++) {
        uint32_t h0, l0, h1, l1;
        split2(acc[t].x, acc[t].y, h0, l0);
        split2(acc[t].z, acc[t].w, h1, l1);
        unsigned long long ph = (unsigned long long)h0 | ((unsigned long long)h1 << 32);
        unsigned long long pl = (unsigned long long)l0 | ((unsigned long long)l1 << 32);
        __stcs((unsigned long long*)(g_mh + (size_t)t * NH) + o, ph);
        __stcs((unsigned long long*)(g_ml + (size_t)t * NH) + o, pl);
    }
}

// ---------------- layer GEMM: cp.async double-buffered, evict-first A ----------
#define GL_AHI 0
#define GL_ALO 10240
#define GL_BHI 20480
#define GL_BLO 29184
#define GL_BUF 37888
#define GL_TOT 75776

__global__ void __launch_bounds__(256, 2) k_gemm_l(
    const uint16_t* __restrict__ mh, const uint16_t* __restrict__ ml,
    const uint16_t* __restrict__ wh, const uint16_t* __restrict__ wl,
    const float* __restrict__ bias, const float* __restrict__ resid,
    float* __restrict__ C, uint16_t* __restrict__ hb_out)
{
    extern __shared__ char smem[];
    uint32_t s0 = smem_u32(smem);
    int tid = threadIdx.x, wid = tid >> 5, lane = tid & 31;
    int row0 = blockIdx.x * 128;
    int warp_m = wid & 1, warp_n = wid >> 1;

    uint64_t pol;
    asm("createpolicy.fractional.L2::evict_first.b64 %0, 1.0;" : "=l"(pol));

    float c[4][4][4];
#pragma unroll
    for (int i = 0; i < 4; i++)
#pragma unroll
        for (int j = 0; j < 4; j++)
#pragma unroll
            for (int q = 0; q < 4; q++) c[i][j][q] = 0.0f;

    auto load_chunk = [&](int ch, int buf) {
        int t = ch >> 2, sub = ch & 3;
        const uint16_t* mhb = mh + (size_t)t * NH + (size_t)row0 * HH + sub * 32;
        const uint16_t* mlb = ml + (size_t)t * NH + (size_t)row0 * HH + sub * 32;
        const uint16_t* whb = wh + (size_t)t * HH * HH + (size_t)(sub * 32) * HH;
        const uint16_t* wlb = wl + (size_t)t * HH * HH + (size_t)(sub * 32) * HH;
        uint32_t sb = s0 + buf * GL_BUF;
#pragma unroll
        for (int q = 0; q < 2; q++) {
            int s = q * 256 + tid;
            int r = s >> 2, part = s & 3;
            cp16_ef(sb + GL_AHI + r * 80 + part * 16, mhb + (size_t)r * HH + part * 8, pol);
            cp16_ef(sb + GL_ALO + r * 80 + part * 16, mlb + (size_t)r * HH + part * 8, pol);
        }
#pragma unroll
        for (int q = 0; q < 2; q++) {
            int s = q * 256 + tid;
            int r = s >> 4, part = s & 15;
            cp16(sb + GL_BHI + r * 272 + part * 16, whb + (size_t)r * HH + part * 8);
            cp16(sb + GL_BLO + r * 272 + part * 16, wlb + (size_t)r * HH + part * 8);
        }
    };

    load_chunk(0, 0);
    asm volatile("cp.async.commit_group;" ::: "memory");

    for (int ch = 0; ch < 16; ch++) {
        if (ch + 1 < 16) {
            load_chunk(ch + 1, (ch + 1) & 1);
            asm volatile("cp.async.commit_group;" ::: "memory");
            asm volatile("cp.async.wait_group 1;" ::: "memory");
        } else {
            asm volatile("cp.async.wait_group 0;" ::: "memory");
        }
        __syncthreads();

        uint32_t sb = s0 + (ch & 1) * GL_BUF;
#pragma unroll
        for (int ks = 0; ks < 2; ks++) {
            uint32_t ah[4][4], al[4][4];
#pragma unroll
            for (int mt = 0; mt < 4; mt++) {
                uint32_t row  = warp_m * 64 + mt * 16 + (lane & 15);
                uint32_t addr = sb + GL_AHI + row * 80 + ks * 32 + ((lane >> 4) << 4);
                ldsm_x4(ah[mt], addr);
                ldsm_x4(al[mt], addr + (GL_ALO - GL_AHI));
            }
#pragma unroll
            for (int np = 0; np < 2; np++) {
                uint32_t kk   = ks * 16 + (lane & 15);
                uint32_t col  = warp_n * 32 + np * 16 + ((lane >> 4) & 1) * 8;
                uint32_t addr = sb + GL_BHI + kk * 272 + col * 2;
                uint32_t bh[4], bl[4];
                ldsm_x4_t(bh, addr);
                ldsm_x4_t(bl, addr + (GL_BLO - GL_BHI));
#pragma unroll
                for (int mt = 0; mt < 4; mt++) {
                    mma_bf16(c[mt][np * 2],     ah[mt], bh);
                    mma_bf16(c[mt][np * 2],     al[mt], bh);
                    mma_bf16(c[mt][np * 2],     ah[mt], bl);
                    mma_bf16(c[mt][np * 2 + 1], ah[mt], bh + 2);
                    mma_bf16(c[mt][np * 2 + 1], al[mt], bh + 2);
                    mma_bf16(c[mt][np * 2 + 1], ah[mt], bl + 2);
                }
            }
        }
        __syncthreads();
    }

#pragma unroll
    for (int mt = 0; mt < 4; mt++) {
#pragma unroll
        for (int nt = 0; nt < 4; nt++) {
            int col = warp_n * 32 + nt * 8 + (lane & 3) * 2;
            float2 bv = *(const float2*)(bias + col);
#pragma unroll
            for (int half = 0; half < 2; half++) {
                long row  = row0 + warp_m * 64 + mt * 16 + (lane >> 2) + half * 8;
                long base = row * HH + col;
                float2 v;
                v.x = fmaxf(c[mt][nt][half * 2 + 0] + bv.x, 0.f);
                v.y = fmaxf(c[mt][nt][half * 2 + 1] + bv.y, 0.f);
                if (resid) {
                    float2 rr = __ldcs((const float2*)(resid + base));
                    v.x += rr.x; v.y += rr.y;
                }
                *(float2*)(C + base) = v;
                if (hb_out)
                    *(uint32_t*)(hb_out + base) = pack_bf16(v.x, v.y);
            }
        }
    }
}

// ---------------- head kernels ----------------
__global__ void k_transpose(const float* __restrict__ Wb) {
    int idx = blockIdx.x * blockDim.x + threadIdx.x;
    if (idx >= HH * HH) return;
    int r = idx >> 7, c = idx & 127;
    g_wbt[c * HH + r] = Wb[idx];
}

__global__ void k_pool(const float* __restrict__ h, const int* __restrict__ pred) {
    int b = blockIdx.x, j = threadIdx.x;
    float acc = 0.0f;
#pragma unroll 4
    for (int p = 0; p < PPG; p++) {
        int node = pred[b * PPG + p];
        acc += h[(size_t)node * HH + j];
    }
    g_pool[b * HH + j] = acc * (1.0f / PPG);
}

__global__ void k_tp() {
    int b = blockIdx.x, hrow = threadIdx.x;
    __shared__ float ps[HH];
    ps[hrow] = g_pool[b * HH + hrow];
    __syncthreads();
    float acc = 0.0f;
#pragma unroll 8
    for (int k = 0; k < HH; k++)
        acc += g_wbt[(size_t)k * HH + hrow] * ps[k];
    g_tp[b * HH + hrow] = acc;
}

__global__ void k_score(const float* __restrict__ h, const int* __restrict__ pred,
                        const float* __restrict__ bbp, float* __restrict__ out)
{
    int b = blockIdx.x;
    int tid = threadIdx.x;
    __shared__ __align__(16) float tps[HH];
    __shared__ float sc[PPG];
    tps[tid] = g_tp[b * HH + tid];
    __syncthreads();
    int warp = tid >> 5, lane = tid & 31;
    float4 tv = ((const float4*)tps)[lane];
    for (int p = warp; p < PPG; p += 4) {
        int node = pred[b * PPG + p];
        float4 hv = ((const float4*)h)[(size_t)node * 32 + lane];
        float d = hv.x * tv.x + hv.y * tv.y + hv.z * tv.z + hv.w * tv.w;
#pragma unroll
        for (int o = 16; o > 0; o >>= 1) d += __shfl_xor_sync(0xffffffffu, d, o);
        if (lane == 0) sc[p] = d + bbp[0];
    }
    __syncthreads();
    if (tid < 32) {
        float v = sc[tid];
        float m = v;
#pragma unroll
        for (int o = 16; o > 0; o >>= 1) m = fmaxf(m, __shfl_xor_sync(0xffffffffu, m, o));
        float e = expf(v - m);
        float s = e;
#pragma unroll
        for (int o = 16; o > 0; o >>= 1) s += __shfl_xor_sync(0xffffffffu, s, o);
        out[b * PPG + tid] = v - m - logf(s);
    }
}

// ---------------- launch ----------------
extern "C" void kernel_launch(void* const* d_in, const int* in_sizes, int n_in,
                              void* d_out, int out_size)
{
    (void)in_sizes; (void)n_in; (void)out_size;
    const float* emb_table = (const float*)d_in[0];
    const float* W_t       = (const float*)d_in[1];
    const float* b_t       = (const float*)d_in[2];
    const float* W_r       = (const float*)d_in[3];
    const float* b_r       = (const float*)d_in[4];
    const float* Wb        = (const float*)d_in[5];
    const float* bb        = (const float*)d_in[6];
    const float* norm      = (const float*)d_in[7];
    const int*   gid       = (const int*)d_in[8];
    const int*   spo       = (const int*)d_in[9];
    const int*   access_   = (const int*)d_in[10];
    const int*   pre       = (const int*)d_in[11];
    const int*   src       = (const int*)d_in[12];
    const int*   dst       = (const int*)d_in[13];
    const int*   etype     = (const int*)d_in[14];
    const int*   pred      = (const int*)d_in[15];
    float* out = (float*)d_out;

    void *p_cnt, *p_h, *p_h2, *p_hb, *p_mh, *p_ml, *p_wh, *p_wl;
    cudaGetSymbolAddress(&p_cnt, g_cnt);
    cudaGetSymbolAddress(&p_h,   g_h);
    cudaGetSymbolAddress(&p_h2,  g_h2);
    cudaGetSymbolAddress(&p_hb,  g_hb);
    cudaGetSymbolAddress(&p_mh,  g_mh);
    cudaGetSymbolAddress(&p_ml,  g_ml);
    cudaGetSymbolAddress(&p_wh,  g_wh);
    cudaGetSymbolAddress(&p_wl,  g_wl);

    const int TPB = 256;
    const int node_warp_blocks = NN / 8;
    const int gemm_blocks      = NN / 128;
    const int proj_blocks      = VPAD / 128;

    cudaFuncSetAttribute(k_proj,   cudaFuncAttributeMaxDynamicSharedMemorySize, SM_TOT);
    cudaFuncSetAttribute(k_gemm_l, cudaFuncAttributeMaxDynamicSharedMemorySize, GL_TOT);

    // --- CSR build + weight split + table projection ---
    cudaMemsetAsync(p_cnt, 0, (size_t)NN * sizeof(int), 0);
    k_count<<<EE / TPB, TPB>>>(dst);
    k_wsplit<<<(2 * 4 * HH * HH) / TPB, TPB>>>(W_r);
    k_proj<<<proj_blocks, TPB, SM_TOT>>>(emb_table, W_t);
    k_scan1<<<128, 256>>>();
    k_scan2<<<1, 128>>>();
    k_scan3<<<128, 256>>>();
    k_fill<<<EE / TPB, TPB>>>(src, dst, etype, norm);

    // --- init: h0 (fp32 + bf16 mirror) ---
    k_init2<<<node_warp_blocks, TPB>>>(gid, spo, access_, pre, W_t, b_t, (float*)p_h);

    // --- layer 0 ---
    k_gather4<<<node_warp_blocks, TPB>>>();
    k_gemm_l<<<gemm_blocks, TPB, GL_TOT>>>((const uint16_t*)p_mh, (const uint16_t*)p_ml,
                                           (const uint16_t*)p_wh, (const uint16_t*)p_wl,
                                           b_r, (const float*)p_h, (float*)p_h2,
                                           (uint16_t*)p_hb);

    // --- layer 1 ---
    k_gather4<<<node_warp_blocks, TPB>>>();
    k_gemm_l<<<gemm_blocks, TPB, GL_TOT>>>((const uint16_t*)p_mh, (const uint16_t*)p_ml,
                                           (const uint16_t*)p_wh + 4 * HH * HH,
                                           (const uint16_t*)p_wl + 4 * HH * HH,
                                           b_r + HH, nullptr, (float*)p_h, nullptr);

    // --- head ---
    k_transpose<<<(HH * HH) / TPB, TPB>>>(Wb);
    k_pool<<<BBG, HH>>>((const float*)p_h, pred);
    k_tp<<<BBG, HH>>>();
    k_score<<<BBG, HH>>>((const float*)p_h, pred, bb, out);
}

// round 14
// speedup vs baseline: 1.3042x; 1.1857x over previous
#include <cuda_runtime.h>
#include <cuda_bf16.h>
#include <cstdint>

#define NN   131072
#define EE   1048576
#define HH   128
#define VV   30000
#define VPAD 30080     // 235 * 128
#define BBG  512
#define PPG  32
#define NH   (NN*HH)

// ---------------- static device scratch ----------------
__device__ float g_ptab[VPAD * HH];    // projected embedding table
__device__ float g_h[NH];
__device__ float g_h2[NH];
__device__ uint16_t g_hb[NH];          // bf16 mirror of current h (gather reads)
__device__ uint16_t g_mh[4ULL * NH];   // mailbox (bf16, single plane)
__device__ uint16_t g_wh[2 * 4 * HH * HH];  // W_r hi
__device__ uint16_t g_wl[2 * 4 * HH * HH];  // W_r lo
__device__ float g_pool[BBG * HH];
__device__ float g_tp[BBG * HH];
__device__ float g_wbt[HH * HH];
// dst-keyed CSR
__device__ int  g_cnt[NN];
__device__ int  g_off[NN + 1];
__device__ int  g_cur[NN];
__device__ int  g_bsum[128];
__device__ int2 g_rec[EE];             // {src | etype<<20, norm bits}

// ---------------- helpers ----------------
__device__ __forceinline__ uint32_t smem_u32(const void* p) {
    uint32_t a;
    asm("{ .reg .u64 t; cvta.to.shared.u64 t, %1; cvt.u32.u64 %0, t; }" : "=r"(a) : "l"(p));
    return a;
}
__device__ __forceinline__ void ldsm_x4(uint32_t r[4], uint32_t addr) {
    asm volatile("ldmatrix.sync.aligned.m8n8.x4.shared.b16 {%0,%1,%2,%3}, [%4];"
                 : "=r"(r[0]), "=r"(r[1]), "=r"(r[2]), "=r"(r[3]) : "r"(addr));
}
__device__ __forceinline__ void ldsm_x4_t(uint32_t r[4], uint32_t addr) {
    asm volatile("ldmatrix.sync.aligned.m8n8.x4.trans.shared.b16 {%0,%1,%2,%3}, [%4];"
                 : "=r"(r[0]), "=r"(r[1]), "=r"(r[2]), "=r"(r[3]) : "r"(addr));
}
__device__ __forceinline__ void mma_bf16(float* c, const uint32_t a[4], const uint32_t* b) {
    asm volatile(
        "mma.sync.aligned.m16n8k16.row.col.f32.bf16.bf16.f32 "
        "{%0,%1,%2,%3}, {%4,%5,%6,%7}, {%8,%9}, {%0,%1,%2,%3};"
        : "+f"(c[0]), "+f"(c[1]), "+f"(c[2]), "+f"(c[3])
        : "r"(a[0]), "r"(a[1]), "r"(a[2]), "r"(a[3]), "r"(b[0]), "r"(b[1]));
}
__device__ __forceinline__ void split2(float a, float b, uint32_t& hi, uint32_t& lo) {
    __nv_bfloat16 ha = __float2bfloat16_rn(a);
    __nv_bfloat16 hb = __float2bfloat16_rn(b);
    __nv_bfloat16 la = __float2bfloat16_rn(a - __bfloat162float(ha));
    __nv_bfloat16 lb = __float2bfloat16_rn(b - __bfloat162float(hb));
    hi = (uint32_t)__bfloat16_as_ushort(ha) | ((uint32_t)__bfloat16_as_ushort(hb) << 16);
    lo = (uint32_t)__bfloat16_as_ushort(la) | ((uint32_t)__bfloat16_as_ushort(lb) << 16);
}
__device__ __forceinline__ uint32_t pack_bf16(float a, float b) {
    __nv_bfloat162 p = __floats2bfloat162_rn(a, b);
    return *reinterpret_cast<uint32_t*>(&p);
}
__device__ __forceinline__ void cp16_ef(uint32_t smem, const void* g, uint64_t pol) {
    asm volatile("cp.async.cg.shared.global.L2::cache_hint [%0], [%1], 16, %2;"
                 :: "r"(smem), "l"(g), "l"(pol));
}
__device__ __forceinline__ void cp16(uint32_t smem, const void* g) {
    asm volatile("cp.async.cg.shared.global [%0], [%1], 16;" :: "r"(smem), "l"(g));
}

// ---------------- CSR build (dst-keyed) ----------------
__global__ void k_count(const int* __restrict__ dst) {
    int e = blockIdx.x * blockDim.x + threadIdx.x;
    if (e >= EE) return;
    atomicAdd(&g_cnt[dst[e]], 1);
}

__global__ void k_scan1() {
    __shared__ int s[256];
    int t = threadIdx.x;
    int4 v = *(const int4*)(g_cnt + blockIdx.x * 1024 + t * 4);
    s[t] = v.x + v.y + v.z + v.w;
    __syncthreads();
    for (int o = 128; o > 0; o >>= 1) {
        if (t < o) s[t] += s[t + o];
        __syncthreads();
    }
    if (t == 0) g_bsum[blockIdx.x] = s[0];
}

__global__ void k_scan2() {
    __shared__ int s[128];
    int t = threadIdx.x;
    int mine = g_bsum[t];
    s[t] = mine;
    __syncthreads();
    for (int o = 1; o < 128; o <<= 1) {
        int add = (t >= o) ? s[t - o] : 0;
        __syncthreads();
        s[t] += add;
        __syncthreads();
    }
    g_bsum[t] = s[t] - mine;
}

__global__ void k_scan3() {
    __shared__ int s[256];
    int t = threadIdx.x;
    int base = blockIdx.x * 1024 + t * 4;
    int4 v = *(const int4*)(g_cnt + base);
    int tsum = v.x + v.y + v.z + v.w;
    s[t] = tsum;
    __syncthreads();
    for (int o = 1; o < 256; o <<= 1) {
        int add = (t >= o) ? s[t - o] : 0;
        __syncthreads();
        s[t] += add;
        __syncthreads();
    }
    int o0 = s[t] - tsum + g_bsum[blockIdx.x];
    int o1 = o0 + v.x, o2 = o1 + v.y, o3 = o2 + v.z;
    *(int4*)(g_off + base) = make_int4(o0, o1, o2, o3);
    *(int4*)(g_cur + base) = make_int4(o0, o1, o2, o3);
    if (base + 4 == NN) g_off[NN] = o3 + v.w;
}

__global__ void k_fill(const int* __restrict__ src, const int* __restrict__ dst,
                       const int* __restrict__ et,  const float* __restrict__ norm) {
    int e = blockIdx.x * blockDim.x + threadIdx.x;
    if (e >= EE) return;
    int p = atomicAdd(&g_cur[dst[e]], 1);
    g_rec[p] = make_int2(src[e] | (et[e] << 20), __float_as_int(norm[e]));
}

// ---------------- weight split ----------------
__global__ void k_wsplit(const float* __restrict__ Wr) {
    int i = blockIdx.x * blockDim.x + threadIdx.x;
    float v = Wr[i];
    __nv_bfloat16 h = __float2bfloat16_rn(v);
    g_wh[i] = __bfloat16_as_ushort(h);
    g_wl[i] = __bfloat16_as_ushort(__float2bfloat16_rn(v - __bfloat162float(h)));
}

// ---------------- projected table: ptab = emb_table @ Wt[:128] ----------------
#define SM_AHI 0
#define SM_ALO 18432
#define SM_BHI 36864
#define SM_BLO 54272
#define SM_TOT 71680

__global__ void __launch_bounds__(256, 2) k_proj(
    const float* __restrict__ A, const float* __restrict__ Wt)
{
    extern __shared__ char smem[];
    uint32_t s0 = smem_u32(smem);
    int tid = threadIdx.x, wid = tid >> 5, lane = tid & 31;
    int row0 = blockIdx.x * 128;
    int warp_m = wid & 1, warp_n = wid >> 1;

    float c[4][4][4];
#pragma unroll
    for (int i = 0; i < 4; i++)
#pragma unroll
        for (int j = 0; j < 4; j++)
#pragma unroll
            for (int q = 0; q < 4; q++) c[i][j][q] = 0.0f;

    for (int ch = 0; ch < 2; ch++) {
        if (tid < 128) {
#pragma unroll
            for (int p = 0; p < 16; p++) {
                int e = p * 128 + tid;
                int r = e >> 4, c4 = e & 15;
                int rg = min(row0 + r, VV - 1);
                float4 v = *(const float4*)(A + (size_t)rg * HH + ch * 64 + c4 * 4);
                uint32_t h0, l0, h1, l1;
                split2(v.x, v.y, h0, l0);
                split2(v.z, v.w, h1, l1);
                uint32_t off = (uint32_t)r * 144 + c4 * 8;
                *(uint2*)(smem + SM_AHI + off) = make_uint2(h0, h1);
                *(uint2*)(smem + SM_ALO + off) = make_uint2(l0, l1);
            }
        } else {
            int t = tid - 128;
            const float* gb = Wt + (size_t)(ch * 64) * HH;
#pragma unroll
            for (int p = 0; p < 16; p++) {
                int e = p * 128 + t;
                int k = e >> 5, c4 = e & 31;
                float4 v = *(const float4*)(gb + (size_t)k * HH + c4 * 4);
                uint32_t h0, l0, h1, l1;
                split2(v.x, v.y, h0, l0);
                split2(v.z, v.w, h1, l1);
                uint32_t off = (uint32_t)k * 272 + c4 * 8;
                *(uint2*)(smem + SM_BHI + off) = make_uint2(h0, h1);
                *(uint2*)(smem + SM_BLO + off) = make_uint2(l0, l1);
            }
        }
        __syncthreads();

#pragma unroll
        for (int ks = 0; ks < 4; ks++) {
            uint32_t ah[4][4], al[4][4];
#pragma unroll
            for (int mt = 0; mt < 4; mt++) {
                uint32_t row  = warp_m * 64 + mt * 16 + (lane & 15);
                uint32_t addr = s0 + SM_AHI + row * 144 + ks * 32 + ((lane >> 4) << 4);
                ldsm_x4(ah[mt], addr);
                ldsm_x4(al[mt], addr + (SM_ALO - SM_AHI));
            }
#pragma unroll
            for (int np = 0; np < 2; np++) {
                uint32_t kk   = ks * 16 + (lane & 15);
                uint32_t col  = warp_n * 32 + np * 16 + ((lane >> 4) & 1) * 8;
                uint32_t addr = s0 + SM_BHI + kk * 272 + col * 2;
                uint32_t bh[4], bl[4];
                ldsm_x4_t(bh, addr);
                ldsm_x4_t(bl, addr + (SM_BLO - SM_BHI));
#pragma unroll
                for (int mt = 0; mt < 4; mt++) {
                    mma_bf16(c[mt][np * 2],     ah[mt], bh);
                    mma_bf16(c[mt][np * 2],     al[mt], bh);
                    mma_bf16(c[mt][np * 2],     ah[mt], bl);
                    mma_bf16(c[mt][np * 2 + 1], ah[mt], bh + 2);
                    mma_bf16(c[mt][np * 2 + 1], al[mt], bh + 2);
                    mma_bf16(c[mt][np * 2 + 1], ah[mt], bl + 2);
                }
            }
        }
        __syncthreads();
    }

#pragma unroll
    for (int mt = 0; mt < 4; mt++) {
#pragma unroll
        for (int nt = 0; nt < 4; nt++) {
            int col = warp_n * 32 + nt * 8 + (lane & 3) * 2;
#pragma unroll
            for (int half = 0; half < 2; half++) {
                long row = row0 + warp_m * 64 + mt * 16 + (lane >> 2) + half * 8;
                if (row < VV)
                    *(float2*)(g_ptab + row * HH + col) =
                        make_float2(c[mt][nt][half * 2 + 0], c[mt][nt][half * 2 + 1]);
            }
        }
    }
}

// ---------------- init: h0 (fp32 + bf16 mirror) from ptab ----------------
__global__ void k_init2(const int* __restrict__ gid, const int* __restrict__ spo,
                        const int* __restrict__ acc_, const int* __restrict__ pre,
                        const float* __restrict__ Wt, const float* __restrict__ bt,
                        float* __restrict__ hout)
{
    __shared__ float sw[768];
    for (int i = threadIdx.x; i < 768; i += blockDim.x)
        sw[i] = (i < 640) ? Wt[(size_t)(128 + (i >> 7)) * HH + (i & 127)] : bt[i - 640];
    __syncthreads();

    int node = (blockIdx.x * blockDim.x + threadIdx.x) >> 5;
    int lane = threadIdx.x & 31;
    if (node >= NN) return;
    int s0 = spo[node * 3 + 0];
    int s1 = spo[node * 3 + 1];
    int s2 = spo[node * 3 + 2];
    int beg = g_off[node], end = g_off[node + 1];

    float4 a = make_float4(0.f, 0.f, 0.f, 0.f);
    bool has_ne = false;
    for (int base = beg; base < end; base += 32) {
        int n = min(32, end - base);
        int2 r = (base + lane < end) ? __ldcs(&g_rec[base + lane]) : make_int2(-1, 0);
        for (int i = 0; i < n; i++) {
            int rx = __shfl_sync(0xffffffffu, r.x, i);
            int rn = __shfl_sync(0xffffffffu, r.y, i);
            if ((rx >> 20) != 0) continue;
            has_ne = true;
            int s = rx & 0xFFFFF;
            float nw = __int_as_float(rn);
            float4 hv = ((const float4*)g_ptab)[(size_t)gid[s] * 32 + lane];
            a.x += hv.x * nw; a.y += hv.y * nw;
            a.z += hv.z * nw; a.w += hv.w * nw;
        }
    }
    float4 e4;
    if ((s0 + s2) > 0 && has_ne) e4 = a;
    else                         e4 = ((const float4*)g_ptab)[(size_t)gid[node] * 32 + lane];

    float cf0 = (float)s0, cf1 = (float)s1, cf2 = (float)s2;
    float cf3 = (float)acc_[node], cf4 = (float)pre[node];
    int col = lane * 4;
#pragma unroll
    for (int q = 0; q < 4; q++) {
        float add = sw[640 + col + q]
                  + cf0 * sw[col + q]       + cf1 * sw[128 + col + q]
                  + cf2 * sw[256 + col + q] + cf3 * sw[384 + col + q]
                  + cf4 * sw[512 + col + q];
        (&e4.x)[q] += add;
    }
    size_t o = (size_t)node * 32 + lane;
    ((float4*)hout)[o] = e4;
    ((uint2*)g_hb)[o] = make_uint2(pack_bf16(e4.x, e4.y), pack_bf16(e4.z, e4.w));
}

// ---------------- gather-first: bf16 h reads, single-plane mailbox ------------
__global__ void k_gather4()
{
    int node = (blockIdx.x * blockDim.x + threadIdx.x) >> 5;
    int lane = threadIdx.x & 31;
    if (node >= NN) return;
    int beg = g_off[node], end = g_off[node + 1];

    float4 a0 = make_float4(0.f, 0.f, 0.f, 0.f);
    float4 a1 = a0, a2 = a0, a3 = a0;
    for (int base = beg; base < end; base += 32) {
        int n = min(32, end - base);
        int2 r = (base + lane < end) ? __ldcs(&g_rec[base + lane]) : make_int2(0, 0);
        for (int i = 0; i < n; i++) {
            int rx = __shfl_sync(0xffffffffu, r.x, i);
            int rn = __shfl_sync(0xffffffffu, r.y, i);
            int s = rx & 0xFFFFF;
            int t = rx >> 20;
            float nw = __int_as_float(rn);
            uint2 pv = ((const uint2*)g_hb)[(size_t)s * 32 + lane];
            float2 f0 = __bfloat1622float2(*reinterpret_cast<__nv_bfloat162*>(&pv.x));
            float2 f1 = __bfloat1622float2(*reinterpret_cast<__nv_bfloat162*>(&pv.y));
            switch (t) {
            case 0: a0.x += f0.x*nw; a0.y += f0.y*nw; a0.z += f1.x*nw; a0.w += f1.y*nw; break;
            case 1: a1.x += f0.x*nw; a1.y += f0.y*nw; a1.z += f1.x*nw; a1.w += f1.y*nw; break;
            case 2: a2.x += f0.x*nw; a2.y += f0.y*nw; a2.z += f1.x*nw; a2.w += f1.y*nw; break;
            default:a3.x += f0.x*nw; a3.y += f0.y*nw; a3.z += f1.x*nw; a3.w += f1.y*nw; break;
            }
        }
    }
    size_t o = (size_t)node * 32 + lane;
    float4 acc[4] = {a0, a1, a2, a3};
#pragma unroll
    for (int t = 0; t < 4; t++) {
        unsigned long long ph =
            (unsigned long long)pack_bf16(acc[t].x, acc[t].y)
          | ((unsigned long long)pack_bf16(acc[t].z, acc[t].w) << 32);
        __stcs((unsigned long long*)(g_mh + (size_t)t * NH) + o, ph);
    }
}

// ---------------- layer GEMM: single-plane A, 2-pass MMA, cp.async pipelined ----
#define GL_AHI 0
#define GL_BHI 10240
#define GL_BLO 18944
#define GL_BUF 27648
#define GL_TOT 55296

__global__ void __launch_bounds__(256, 2) k_gemm_l(
    const uint16_t* __restrict__ mh,
    const uint16_t* __restrict__ wh, const uint16_t* __restrict__ wl,
    const float* __restrict__ bias, const float* __restrict__ resid,
    float* __restrict__ C, uint16_t* __restrict__ hb_out)
{
    extern __shared__ char smem[];
    uint32_t s0 = smem_u32(smem);
    int tid = threadIdx.x, wid = tid >> 5, lane = tid & 31;
    int row0 = blockIdx.x * 128;
    int warp_m = wid & 1, warp_n = wid >> 1;

    uint64_t pol;
    asm("createpolicy.fractional.L2::evict_first.b64 %0, 1.0;" : "=l"(pol));

    float c[4][4][4];
#pragma unroll
    for (int i = 0; i < 4; i++)
#pragma unroll
        for (int j = 0; j < 4; j++)
#pragma unroll
            for (int q = 0; q < 4; q++) c[i][j][q] = 0.0f;

    auto load_chunk = [&](int ch, int buf) {
        int t = ch >> 2, sub = ch & 3;
        const uint16_t* mhb = mh + (size_t)t * NH + (size_t)row0 * HH + sub * 32;
        const uint16_t* whb = wh + (size_t)t * HH * HH + (size_t)(sub * 32) * HH;
        const uint16_t* wlb = wl + (size_t)t * HH * HH + (size_t)(sub * 32) * HH;
        uint32_t sb = s0 + buf * GL_BUF;
        // A: 128 rows x 32 bf16 = 512 x 16B segs
#pragma unroll
        for (int q = 0; q < 2; q++) {
            int s = q * 256 + tid;
            int r = s >> 2, part = s & 3;
            cp16_ef(sb + GL_AHI + r * 80 + part * 16, mhb + (size_t)r * HH + part * 8, pol);
        }
        // B: 32 rows x 128 bf16, hi + lo
#pragma unroll
        for (int q = 0; q < 2; q++) {
            int s = q * 256 + tid;
            int r = s >> 4, part = s & 15;
            cp16(sb + GL_BHI + r * 272 + part * 16, whb + (size_t)r * HH + part * 8);
            cp16(sb + GL_BLO + r * 272 + part * 16, wlb + (size_t)r * HH + part * 8);
        }
    };

    load_chunk(0, 0);
    asm volatile("cp.async.commit_group;" ::: "memory");

    for (int ch = 0; ch < 16; ch++) {
        if (ch + 1 < 16) {
            load_chunk(ch + 1, (ch + 1) & 1);
            asm volatile("cp.async.commit_group;" ::: "memory");
            asm volatile("cp.async.wait_group 1;" ::: "memory");
        } else {
            asm volatile("cp.async.wait_group 0;" ::: "memory");
        }
        __syncthreads();

        uint32_t sb = s0 + (ch & 1) * GL_BUF;
#pragma unroll
        for (int ks = 0; ks < 2; ks++) {
            uint32_t ah[4][4];
#pragma unroll
            for (int mt = 0; mt < 4; mt++) {
                uint32_t row  = warp_m * 64 + mt * 16 + (lane & 15);
                uint32_t addr = sb + GL_AHI + row * 80 + ks * 32 + ((lane >> 4) << 4);
                ldsm_x4(ah[mt], addr);
            }
#pragma unroll
            for (int np = 0; np < 2; np++) {
                uint32_t kk   = ks * 16 + (lane & 15);
                uint32_t col  = warp_n * 32 + np * 16 + ((lane >> 4) & 1) * 8;
                uint32_t addr = sb + GL_BHI + kk * 272 + col * 2;
                uint32_t bh[4], bl[4];
                ldsm_x4_t(bh, addr);
                ldsm_x4_t(bl, addr + (GL_BLO - GL_BHI));
#pragma unroll
                for (int mt = 0; mt < 4; mt++) {
                    mma_bf16(c[mt][np * 2],     ah[mt], bh);
                    mma_bf16(c[mt][np * 2],     ah[mt], bl);
                    mma_bf16(c[mt][np * 2 + 1], ah[mt], bh + 2);
                    mma_bf16(c[mt][np * 2 + 1], ah[mt], bl + 2);
                }
            }
        }
        __syncthreads();
    }

#pragma unroll
    for (int mt = 0; mt < 4; mt++) {
#pragma unroll
        for (int nt = 0; nt < 4; nt++) {
            int col = warp_n * 32 + nt * 8 + (lane & 3) * 2;
            float2 bv = *(const float2*)(bias + col);
#pragma unroll
            for (int half = 0; half < 2; half++) {
                long row  = row0 + warp_m * 64 + mt * 16 + (lane >> 2) + half * 8;
                long base = row * HH + col;
                float2 v;
                v.x = fmaxf(c[mt][nt][half * 2 + 0] + bv.x, 0.f);
                v.y = fmaxf(c[mt][nt][half * 2 + 1] + bv.y, 0.f);
                if (resid) {
                    float2 rr = __ldcs((const float2*)(resid + base));
                    v.x += rr.x; v.y += rr.y;
                }
                *(float2*)(C + base) = v;
                if (hb_out)
                    *(uint32_t*)(hb_out + base) = pack_bf16(v.x, v.y);
            }
        }
    }
}

// ---------------- head kernels ----------------
__global__ void k_transpose(const float* __restrict__ Wb) {
    int idx = blockIdx.x * blockDim.x + threadIdx.x;
    if (idx >= HH * HH) return;
    int r = idx >> 7, c = idx & 127;
    g_wbt[c * HH + r] = Wb[idx];
}

__global__ void k_pool(const float* __restrict__ h, const int* __restrict__ pred) {
    int b = blockIdx.x, j = threadIdx.x;
    float acc = 0.0f;
#pragma unroll 4
    for (int p = 0; p < PPG; p++) {
        int node = pred[b * PPG + p];
        acc += h[(size_t)node * HH + j];
    }
    g_pool[b * HH + j] = acc * (1.0f / PPG);
}

__global__ void k_tp() {
    int b = blockIdx.x, hrow = threadIdx.x;
    __shared__ float ps[HH];
    ps[hrow] = g_pool[b * HH + hrow];
    __syncthreads();
    float acc = 0.0f;
#pragma unroll 8
    for (int k = 0; k < HH; k++)
        acc += g_wbt[(size_t)k * HH + hrow] * ps[k];
    g_tp[b * HH + hrow] = acc;
}

__global__ void k_score(const float* __restrict__ h, const int* __restrict__ pred,
                        const float* __restrict__ bbp, float* __restrict__ out)
{
    int b = blockIdx.x;
    int tid = threadIdx.x;
    __shared__ __align__(16) float tps[HH];
    __shared__ float sc[PPG];
    tps[tid] = g_tp[b * HH + tid];
    __syncthreads();
    int warp = tid >> 5, lane = tid & 31;
    float4 tv = ((const float4*)tps)[lane];
    for (int p = warp; p < PPG; p += 4) {
        int node = pred[b * PPG + p];
        float4 hv = ((const float4*)h)[(size_t)node * 32 + lane];
        float d = hv.x * tv.x + hv.y * tv.y + hv.z * tv.z + hv.w * tv.w;
#pragma unroll
        for (int o = 16; o > 0; o >>= 1) d += __shfl_xor_sync(0xffffffffu, d, o);
        if (lane == 0) sc[p] = d + bbp[0];
    }
    __syncthreads();
    if (tid < 32) {
        float v = sc[tid];
        float m = v;
#pragma unroll
        for (int o = 16; o > 0; o >>= 1) m = fmaxf(m, __shfl_xor_sync(0xffffffffu, m, o));
        float e = expf(v - m);
        float s = e;
#pragma unroll
        for (int o = 16; o > 0; o >>= 1) s += __shfl_xor_sync(0xffffffffu, s, o);
        out[b * PPG + tid] = v - m - logf(s);
    }
}

// ---------------- launch ----------------
extern "C" void kernel_launch(void* const* d_in, const int* in_sizes, int n_in,
                              void* d_out, int out_size)
{
    (void)in_sizes; (void)n_in; (void)out_size;
    const float* emb_table = (const float*)d_in[0];
    const float* W_t       = (const float*)d_in[1];
    const float* b_t       = (const float*)d_in[2];
    const float* W_r       = (const float*)d_in[3];
    const float* b_r       = (const float*)d_in[4];
    const float* Wb        = (const float*)d_in[5];
    const float* bb        = (const float*)d_in[6];
    const float* norm      = (const float*)d_in[7];
    const int*   gid       = (const int*)d_in[8];
    const int*   spo       = (const int*)d_in[9];
    const int*   access_   = (const int*)d_in[10];
    const int*   pre       = (const int*)d_in[11];
    const int*   src       = (const int*)d_in[12];
    const int*   dst       = (const int*)d_in[13];
    const int*   etype     = (const int*)d_in[14];
    const int*   pred      = (const int*)d_in[15];
    float* out = (float*)d_out;

    void *p_cnt, *p_h, *p_h2, *p_hb, *p_mh, *p_wh, *p_wl;
    cudaGetSymbolAddress(&p_cnt, g_cnt);
    cudaGetSymbolAddress(&p_h,   g_h);
    cudaGetSymbolAddress(&p_h2,  g_h2);
    cudaGetSymbolAddress(&p_hb,  g_hb);
    cudaGetSymbolAddress(&p_mh,  g_mh);
    cudaGetSymbolAddress(&p_wh,  g_wh);
    cudaGetSymbolAddress(&p_wl,  g_wl);

    const int TPB = 256;
    const int node_warp_blocks = NN / 8;
    const int gemm_blocks      = NN / 128;
    const int proj_blocks      = VPAD / 128;

    cudaFuncSetAttribute(k_proj,   cudaFuncAttributeMaxDynamicSharedMemorySize, SM_TOT);
    cudaFuncSetAttribute(k_gemm_l, cudaFuncAttributeMaxDynamicSharedMemorySize, GL_TOT);

    // --- CSR build + weight split + table projection ---
    cudaMemsetAsync(p_cnt, 0, (size_t)NN * sizeof(int), 0);
    k_count<<<EE / TPB, TPB>>>(dst);
    k_wsplit<<<(2 * 4 * HH * HH) / TPB, TPB>>>(W_r);
    k_proj<<<proj_blocks, TPB, SM_TOT>>>(emb_table, W_t);
    k_scan1<<<128, 256>>>();
    k_scan2<<<1, 128>>>();
    k_scan3<<<128, 256>>>();
    k_fill<<<EE / TPB, TPB>>>(src, dst, etype, norm);

    // --- init: h0 (fp32 + bf16 mirror) ---
    k_init2<<<node_warp_blocks, TPB>>>(gid, spo, access_, pre, W_t, b_t, (float*)p_h);

    // --- layer 0 ---
    k_gather4<<<node_warp_blocks, TPB>>>();
    k_gemm_l<<<gemm_blocks, TPB, GL_TOT>>>((const uint16_t*)p_mh,
                                           (const uint16_t*)p_wh, (const uint16_t*)p_wl,
                                           b_r, (const float*)p_h, (float*)p_h2,
                                           (uint16_t*)p_hb);

    // --- layer 1 ---
    k_gather4<<<node_warp_blocks, TPB>>>();
    k_gemm_l<<<gemm_blocks, TPB, GL_TOT>>>((const uint16_t*)p_mh,
                                           (const uint16_t*)p_wh + 4 * HH * HH,
                                           (const uint16_t*)p_wl + 4 * HH * HH,
                                           b_r + HH, nullptr, (float*)p_h, nullptr);

    // --- head ---
    k_transpose<<<(HH * HH) / TPB, TPB>>>(Wb);
    k_pool<<<BBG, HH>>>((const float*)p_h, pred);
    k_tp<<<BBG, HH>>>();
    k_score<<<BBG, HH>>>((const float*)p_h, pred, bb, out);
}

// round 15
// speedup vs baseline: 1.4510x; 1.1126x over previous
#include <cuda_runtime.h>
#include <cuda_bf16.h>
#include <cstdint>

#define NN   131072
#define EE   1048576
#define HH   128
#define VV   30000
#define VPAD 30080     // 235 * 128
#define BBG  512
#define PPG  32
#define NH   (NN*HH)

// ---------------- static device scratch ----------------
__device__ float g_ptab[VPAD * HH];    // projected embedding table (fp32)
__device__ uint16_t g_ptb[VPAD * HH];  // bf16 mirror of ptab
__device__ float g_h[NH];
__device__ float g_h2[NH];
__device__ uint16_t g_hb[NH];          // bf16 mirror of current h (gather reads)
__device__ uint16_t g_mh[4ULL * NH];   // mailbox (bf16, single plane)
__device__ uint16_t g_wh[2 * 4 * HH * HH];  // W_r (bf16, single plane)
__device__ float g_pool[BBG * HH];
__device__ float g_tp[BBG * HH];
__device__ float g_wbt[HH * HH];
// dst-keyed CSR
__device__ int  g_cnt[NN];
__device__ int  g_off[NN + 1];
__device__ int  g_cur[NN];
__device__ int  g_bsum[128];
__device__ int2 g_rec[EE];             // {src | etype<<20, norm bits}

// ---------------- helpers ----------------
__device__ __forceinline__ uint32_t smem_u32(const void* p) {
    uint32_t a;
    asm("{ .reg .u64 t; cvta.to.shared.u64 t, %1; cvt.u32.u64 %0, t; }" : "=r"(a) : "l"(p));
    return a;
}
__device__ __forceinline__ void ldsm_x4(uint32_t r[4], uint32_t addr) {
    asm volatile("ldmatrix.sync.aligned.m8n8.x4.shared.b16 {%0,%1,%2,%3}, [%4];"
                 : "=r"(r[0]), "=r"(r[1]), "=r"(r[2]), "=r"(r[3]) : "r"(addr));
}
__device__ __forceinline__ void ldsm_x4_t(uint32_t r[4], uint32_t addr) {
    asm volatile("ldmatrix.sync.aligned.m8n8.x4.trans.shared.b16 {%0,%1,%2,%3}, [%4];"
                 : "=r"(r[0]), "=r"(r[1]), "=r"(r[2]), "=r"(r[3]) : "r"(addr));
}
__device__ __forceinline__ void mma_bf16(float* c, const uint32_t a[4], const uint32_t* b) {
    asm volatile(
        "mma.sync.aligned.m16n8k16.row.col.f32.bf16.bf16.f32 "
        "{%0,%1,%2,%3}, {%4,%5,%6,%7}, {%8,%9}, {%0,%1,%2,%3};"
        : "+f"(c[0]), "+f"(c[1]), "+f"(c[2]), "+f"(c[3])
        : "r"(a[0]), "r"(a[1]), "r"(a[2]), "r"(a[3]), "r"(b[0]), "r"(b[1]));
}
__device__ __forceinline__ void split2(float a, float b, uint32_t& hi, uint32_t& lo) {
    __nv_bfloat16 ha = __float2bfloat16_rn(a);
    __nv_bfloat16 hb = __float2bfloat16_rn(b);
    __nv_bfloat16 la = __float2bfloat16_rn(a - __bfloat162float(ha));
    __nv_bfloat16 lb = __float2bfloat16_rn(b - __bfloat162float(hb));
    hi = (uint32_t)__bfloat16_as_ushort(ha) | ((uint32_t)__bfloat16_as_ushort(hb) << 16);
    lo = (uint32_t)__bfloat16_as_ushort(la) | ((uint32_t)__bfloat16_as_ushort(lb) << 16);
}
__device__ __forceinline__ uint32_t pack_bf16(float a, float b) {
    __nv_bfloat162 p = __floats2bfloat162_rn(a, b);
    return *reinterpret_cast<uint32_t*>(&p);
}
__device__ __forceinline__ void cp16_ef(uint32_t smem, const void* g, uint64_t pol) {
    asm volatile("cp.async.cg.shared.global.L2::cache_hint [%0], [%1], 16, %2;"
                 :: "r"(smem), "l"(g), "l"(pol));
}
__device__ __forceinline__ void cp16(uint32_t smem, const void* g) {
    asm volatile("cp.async.cg.shared.global [%0], [%1], 16;" :: "r"(smem), "l"(g));
}

// ---------------- CSR build (dst-keyed) ----------------
__global__ void k_count(const int* __restrict__ dst) {
    int e = blockIdx.x * blockDim.x + threadIdx.x;
    if (e >= EE) return;
    atomicAdd(&g_cnt[dst[e]], 1);
}

__global__ void k_scan1() {
    __shared__ int s[256];
    int t = threadIdx.x;
    int4 v = *(const int4*)(g_cnt + blockIdx.x * 1024 + t * 4);
    s[t] = v.x + v.y + v.z + v.w;
    __syncthreads();
    for (int o = 128; o > 0; o >>= 1) {
        if (t < o) s[t] += s[t + o];
        __syncthreads();
    }
    if (t == 0) g_bsum[blockIdx.x] = s[0];
}

__global__ void k_scan2() {
    __shared__ int s[128];
    int t = threadIdx.x;
    int mine = g_bsum[t];
    s[t] = mine;
    __syncthreads();
    for (int o = 1; o < 128; o <<= 1) {
        int add = (t >= o) ? s[t - o] : 0;
        __syncthreads();
        s[t] += add;
        __syncthreads();
    }
    g_bsum[t] = s[t] - mine;
}

__global__ void k_scan3() {
    __shared__ int s[256];
    int t = threadIdx.x;
    int base = blockIdx.x * 1024 + t * 4;
    int4 v = *(const int4*)(g_cnt + base);
    int tsum = v.x + v.y + v.z + v.w;
    s[t] = tsum;
    __syncthreads();
    for (int o = 1; o < 256; o <<= 1) {
        int add = (t >= o) ? s[t - o] : 0;
        __syncthreads();
        s[t] += add;
        __syncthreads();
    }
    int o0 = s[t] - tsum + g_bsum[blockIdx.x];
    int o1 = o0 + v.x, o2 = o1 + v.y, o3 = o2 + v.z;
    *(int4*)(g_off + base) = make_int4(o0, o1, o2, o3);
    *(int4*)(g_cur + base) = make_int4(o0, o1, o2, o3);
    if (base + 4 == NN) g_off[NN] = o3 + v.w;
}

__global__ void k_fill(const int* __restrict__ src, const int* __restrict__ dst,
                       const int* __restrict__ et,  const float* __restrict__ norm) {
    int e = blockIdx.x * blockDim.x + threadIdx.x;
    if (e >= EE) return;
    int p = atomicAdd(&g_cur[dst[e]], 1);
    g_rec[p] = make_int2(src[e] | (et[e] << 20), __float_as_int(norm[e]));
}

// ---------------- weight cast (bf16 single plane) ----------------
__global__ void k_wsplit(const float* __restrict__ Wr) {
    int i = blockIdx.x * blockDim.x + threadIdx.x;
    g_wh[i] = __bfloat16_as_ushort(__float2bfloat16_rn(Wr[i]));
}

// ---------------- projected table: ptab = emb_table @ Wt[:128] ----------------
#define SM_AHI 0
#define SM_ALO 18432
#define SM_BHI 36864
#define SM_BLO 54272
#define SM_TOT 71680

__global__ void __launch_bounds__(256, 2) k_proj(
    const float* __restrict__ A, const float* __restrict__ Wt)
{
    extern __shared__ char smem[];
    uint32_t s0 = smem_u32(smem);
    int tid = threadIdx.x, wid = tid >> 5, lane = tid & 31;
    int row0 = blockIdx.x * 128;
    int warp_m = wid & 1, warp_n = wid >> 1;

    float c[4][4][4];
#pragma unroll
    for (int i = 0; i < 4; i++)
#pragma unroll
        for (int j = 0; j < 4; j++)
#pragma unroll
            for (int q = 0; q < 4; q++) c[i][j][q] = 0.0f;

    for (int ch = 0; ch < 2; ch++) {
        if (tid < 128) {
#pragma unroll
            for (int p = 0; p < 16; p++) {
                int e = p * 128 + tid;
                int r = e >> 4, c4 = e & 15;
                int rg = min(row0 + r, VV - 1);
                float4 v = *(const float4*)(A + (size_t)rg * HH + ch * 64 + c4 * 4);
                uint32_t h0, l0, h1, l1;
                split2(v.x, v.y, h0, l0);
                split2(v.z, v.w, h1, l1);
                uint32_t off = (uint32_t)r * 144 + c4 * 8;
                *(uint2*)(smem + SM_AHI + off) = make_uint2(h0, h1);
                *(uint2*)(smem + SM_ALO + off) = make_uint2(l0, l1);
            }
        } else {
            int t = tid - 128;
            const float* gb = Wt + (size_t)(ch * 64) * HH;
#pragma unroll
            for (int p = 0; p < 16; p++) {
                int e = p * 128 + t;
                int k = e >> 5, c4 = e & 31;
                float4 v = *(const float4*)(gb + (size_t)k * HH + c4 * 4);
                uint32_t h0, l0, h1, l1;
                split2(v.x, v.y, h0, l0);
                split2(v.z, v.w, h1, l1);
                uint32_t off = (uint32_t)k * 272 + c4 * 8;
                *(uint2*)(smem + SM_BHI + off) = make_uint2(h0, h1);
                *(uint2*)(smem + SM_BLO + off) = make_uint2(l0, l1);
            }
        }
        __syncthreads();

#pragma unroll
        for (int ks = 0; ks < 4; ks++) {
            uint32_t ah[4][4], al[4][4];
#pragma unroll
            for (int mt = 0; mt < 4; mt++) {
                uint32_t row  = warp_m * 64 + mt * 16 + (lane & 15);
                uint32_t addr = s0 + SM_AHI + row * 144 + ks * 32 + ((lane >> 4) << 4);
                ldsm_x4(ah[mt], addr);
                ldsm_x4(al[mt], addr + (SM_ALO - SM_AHI));
            }
#pragma unroll
            for (int np = 0; np < 2; np++) {
                uint32_t kk   = ks * 16 + (lane & 15);
                uint32_t col  = warp_n * 32 + np * 16 + ((lane >> 4) & 1) * 8;
                uint32_t addr = s0 + SM_BHI + kk * 272 + col * 2;
                uint32_t bh[4], bl[4];
                ldsm_x4_t(bh, addr);
                ldsm_x4_t(bl, addr + (SM_BLO - SM_BHI));
#pragma unroll
                for (int mt = 0; mt < 4; mt++) {
                    mma_bf16(c[mt][np * 2],     ah[mt], bh);
                    mma_bf16(c[mt][np * 2],     al[mt], bh);
                    mma_bf16(c[mt][np * 2],     ah[mt], bl);
                    mma_bf16(c[mt][np * 2 + 1], ah[mt], bh + 2);
                    mma_bf16(c[mt][np * 2 + 1], al[mt], bh + 2);
                    mma_bf16(c[mt][np * 2 + 1], ah[mt], bl + 2);
                }
            }
        }
        __syncthreads();
    }

#pragma unroll
    for (int mt = 0; mt < 4; mt++) {
#pragma unroll
        for (int nt = 0; nt < 4; nt++) {
            int col = warp_n * 32 + nt * 8 + (lane & 3) * 2;
#pragma unroll
            for (int half = 0; half < 2; half++) {
                long row = row0 + warp_m * 64 + mt * 16 + (lane >> 2) + half * 8;
                if (row < VV) {
                    float2 v = make_float2(c[mt][nt][half * 2 + 0], c[mt][nt][half * 2 + 1]);
                    *(float2*)(g_ptab + row * HH + col) = v;
                    *(uint32_t*)(g_ptb + row * HH + col) = pack_bf16(v.x, v.y);
                }
            }
        }
    }
}

// ---------------- init: h0 (fp32 + bf16 mirror) from ptab ----------------
__global__ void k_init2(const int* __restrict__ gid, const int* __restrict__ spo,
                        const int* __restrict__ acc_, const int* __restrict__ pre,
                        const float* __restrict__ Wt, const float* __restrict__ bt,
                        float* __restrict__ hout)
{
    __shared__ float sw[768];
    for (int i = threadIdx.x; i < 768; i += blockDim.x)
        sw[i] = (i < 640) ? Wt[(size_t)(128 + (i >> 7)) * HH + (i & 127)] : bt[i - 640];
    __syncthreads();

    int node = (blockIdx.x * blockDim.x + threadIdx.x) >> 5;
    int lane = threadIdx.x & 31;
    if (node >= NN) return;
    int s0 = spo[node * 3 + 0];
    int s1 = spo[node * 3 + 1];
    int s2 = spo[node * 3 + 2];
    int beg = g_off[node], end = g_off[node + 1];

    float4 a = make_float4(0.f, 0.f, 0.f, 0.f);
    bool has_ne = false;
    for (int base = beg; base < end; base += 32) {
        int n = min(32, end - base);
        int2 r = (base + lane < end) ? __ldcs(&g_rec[base + lane]) : make_int2(-1, 0);
        for (int i = 0; i < n; i++) {
            int rx = __shfl_sync(0xffffffffu, r.x, i);
            int rn = __shfl_sync(0xffffffffu, r.y, i);
            if ((rx >> 20) != 0) continue;
            has_ne = true;
            int s = rx & 0xFFFFF;
            float nw = __int_as_float(rn);
            uint2 pv = ((const uint2*)g_ptb)[(size_t)gid[s] * 32 + lane];
            float2 f0 = __bfloat1622float2(*reinterpret_cast<__nv_bfloat162*>(&pv.x));
            float2 f1 = __bfloat1622float2(*reinterpret_cast<__nv_bfloat162*>(&pv.y));
            a.x += f0.x * nw; a.y += f0.y * nw;
            a.z += f1.x * nw; a.w += f1.y * nw;
        }
    }
    float4 e4;
    if ((s0 + s2) > 0 && has_ne) e4 = a;
    else                         e4 = ((const float4*)g_ptab)[(size_t)gid[node] * 32 + lane];

    float cf0 = (float)s0, cf1 = (float)s1, cf2 = (float)s2;
    float cf3 = (float)acc_[node], cf4 = (float)pre[node];
    int col = lane * 4;
#pragma unroll
    for (int q = 0; q < 4; q++) {
        float add = sw[640 + col + q]
                  + cf0 * sw[col + q]       + cf1 * sw[128 + col + q]
                  + cf2 * sw[256 + col + q] + cf3 * sw[384 + col + q]
                  + cf4 * sw[512 + col + q];
        (&e4.x)[q] += add;
    }
    size_t o = (size_t)node * 32 + lane;
    ((float4*)hout)[o] = e4;
    ((uint2*)g_hb)[o] = make_uint2(pack_bf16(e4.x, e4.y), pack_bf16(e4.z, e4.w));
}

// ---------------- gather-first: bf16 h reads, single-plane mailbox ------------
__global__ void k_gather4()
{
    int node = (blockIdx.x * blockDim.x + threadIdx.x) >> 5;
    int lane = threadIdx.x & 31;
    if (node >= NN) return;
    int beg = g_off[node], end = g_off[node + 1];

    float4 a0 = make_float4(0.f, 0.f, 0.f, 0.f);
    float4 a1 = a0, a2 = a0, a3 = a0;
    for (int base = beg; base < end; base += 32) {
        int n = min(32, end - base);
        int2 r = (base + lane < end) ? __ldcs(&g_rec[base + lane]) : make_int2(0, 0);
        for (int i = 0; i < n; i++) {
            int rx = __shfl_sync(0xffffffffu, r.x, i);
            int rn = __shfl_sync(0xffffffffu, r.y, i);
            int s = rx & 0xFFFFF;
            int t = rx >> 20;
            float nw = __int_as_float(rn);
            uint2 pv = ((const uint2*)g_hb)[(size_t)s * 32 + lane];
            float2 f0 = __bfloat1622float2(*reinterpret_cast<__nv_bfloat162*>(&pv.x));
            float2 f1 = __bfloat1622float2(*reinterpret_cast<__nv_bfloat162*>(&pv.y));
            switch (t) {
            case 0: a0.x += f0.x*nw; a0.y += f0.y*nw; a0.z += f1.x*nw; a0.w += f1.y*nw; break;
            case 1: a1.x += f0.x*nw; a1.y += f0.y*nw; a1.z += f1.x*nw; a1.w += f1.y*nw; break;
            case 2: a2.x += f0.x*nw; a2.y += f0.y*nw; a2.z += f1.x*nw; a2.w += f1.y*nw; break;
            default:a3.x += f0.x*nw; a3.y += f0.y*nw; a3.z += f1.x*nw; a3.w += f1.y*nw; break;
            }
        }
    }
    size_t o = (size_t)node * 32 + lane;
    float4 acc[4] = {a0, a1, a2, a3};
#pragma unroll
    for (int t = 0; t < 4; t++) {
        unsigned long long ph =
            (unsigned long long)pack_bf16(acc[t].x, acc[t].y)
          | ((unsigned long long)pack_bf16(acc[t].z, acc[t].w) << 32);
        __stcs((unsigned long long*)(g_mh + (size_t)t * NH) + o, ph);
    }
}

// ---------------- layer GEMM: plain bf16, 1-pass MMA, cp.async pipelined ------
#define GL_AHI 0
#define GL_BHI 10240
#define GL_BUF 18944
#define GL_TOT 37888

__global__ void __launch_bounds__(256, 2) k_gemm_l(
    const uint16_t* __restrict__ mh, const uint16_t* __restrict__ wh,
    const float* __restrict__ bias, const float* __restrict__ resid,
    float* __restrict__ C, uint16_t* __restrict__ hb_out)
{
    extern __shared__ char smem[];
    uint32_t s0 = smem_u32(smem);
    int tid = threadIdx.x, wid = tid >> 5, lane = tid & 31;
    int row0 = blockIdx.x * 128;
    int warp_m = wid & 1, warp_n = wid >> 1;

    uint64_t pol;
    asm("createpolicy.fractional.L2::evict_first.b64 %0, 1.0;" : "=l"(pol));

    float c[4][4][4];
#pragma unroll
    for (int i = 0; i < 4; i++)
#pragma unroll
        for (int j = 0; j < 4; j++)
#pragma unroll
            for (int q = 0; q < 4; q++) c[i][j][q] = 0.0f;

    auto load_chunk = [&](int ch, int buf) {
        int t = ch >> 2, sub = ch & 3;
        const uint16_t* mhb = mh + (size_t)t * NH + (size_t)row0 * HH + sub * 32;
        const uint16_t* whb = wh + (size_t)t * HH * HH + (size_t)(sub * 32) * HH;
        uint32_t sb = s0 + buf * GL_BUF;
        // A: 128 rows x 32 bf16 = 512 x 16B segs
#pragma unroll
        for (int q = 0; q < 2; q++) {
            int s = q * 256 + tid;
            int r = s >> 2, part = s & 3;
            cp16_ef(sb + GL_AHI + r * 80 + part * 16, mhb + (size_t)r * HH + part * 8, pol);
        }
        // B: 32 rows x 128 bf16 = 512 x 16B segs
#pragma unroll
        for (int q = 0; q < 2; q++) {
            int s = q * 256 + tid;
            int r = s >> 4, part = s & 15;
            cp16(sb + GL_BHI + r * 272 + part * 16, whb + (size_t)r * HH + part * 8);
        }
    };

    load_chunk(0, 0);
    asm volatile("cp.async.commit_group;" ::: "memory");

    for (int ch = 0; ch < 16; ch++) {
        if (ch + 1 < 16) {
            load_chunk(ch + 1, (ch + 1) & 1);
            asm volatile("cp.async.commit_group;" ::: "memory");
            asm volatile("cp.async.wait_group 1;" ::: "memory");
        } else {
            asm volatile("cp.async.wait_group 0;" ::: "memory");
        }
        __syncthreads();

        uint32_t sb = s0 + (ch & 1) * GL_BUF;
#pragma unroll
        for (int ks = 0; ks < 2; ks++) {
            uint32_t ah[4][4];
#pragma unroll
            for (int mt = 0; mt < 4; mt++) {
                uint32_t row  = warp_m * 64 + mt * 16 + (lane & 15);
                uint32_t addr = sb + GL_AHI + row * 80 + ks * 32 + ((lane >> 4) << 4);
                ldsm_x4(ah[mt], addr);
            }
#pragma unroll
            for (int np = 0; np < 2; np++) {
                uint32_t kk   = ks * 16 + (lane & 15);
                uint32_t col  = warp_n * 32 + np * 16 + ((lane >> 4) & 1) * 8;
                uint32_t addr = sb + GL_BHI + kk * 272 + col * 2;
                uint32_t bh[4];
                ldsm_x4_t(bh, addr);
#pragma unroll
                for (int mt = 0; mt < 4; mt++) {
                    mma_bf16(c[mt][np * 2],     ah[mt], bh);
                    mma_bf16(c[mt][np * 2 + 1], ah[mt], bh + 2);
                }
            }
        }
        __syncthreads();
    }

#pragma unroll
    for (int mt = 0; mt < 4; mt++) {
#pragma unroll
        for (int nt = 0; nt < 4; nt++) {
            int col = warp_n * 32 + nt * 8 + (lane & 3) * 2;
            float2 bv = *(const float2*)(bias + col);
#pragma unroll
            for (int half = 0; half < 2; half++) {
                long row  = row0 + warp_m * 64 + mt * 16 + (lane >> 2) + half * 8;
                long base = row * HH + col;
                float2 v;
                v.x = fmaxf(c[mt][nt][half * 2 + 0] + bv.x, 0.f);
                v.y = fmaxf(c[mt][nt][half * 2 + 1] + bv.y, 0.f);
                if (resid) {
                    float2 rr = __ldcs((const float2*)(resid + base));
                    v.x += rr.x; v.y += rr.y;
                }
                *(float2*)(C + base) = v;
                if (hb_out)
                    *(uint32_t*)(hb_out + base) = pack_bf16(v.x, v.y);
            }
        }
    }
}

// ---------------- head kernels ----------------
__global__ void k_transpose(const float* __restrict__ Wb) {
    int idx = blockIdx.x * blockDim.x + threadIdx.x;
    if (idx >= HH * HH) return;
    int r = idx >> 7, c = idx & 127;
    g_wbt[c * HH + r] = Wb[idx];
}

__global__ void k_pool(const float* __restrict__ h, const int* __restrict__ pred) {
    int b = blockIdx.x, j = threadIdx.x;
    float acc = 0.0f;
#pragma unroll 4
    for (int p = 0; p < PPG; p++) {
        int node = pred[b * PPG + p];
        acc += h[(size_t)node * HH + j];
    }
    g_pool[b * HH + j] = acc * (1.0f / PPG);
}

__global__ void k_tp() {
    int b = blockIdx.x, hrow = threadIdx.x;
    __shared__ float ps[HH];
    ps[hrow] = g_pool[b * HH + hrow];
    __syncthreads();
    float acc = 0.0f;
#pragma unroll 8
    for (int k = 0; k < HH; k++)
        acc += g_wbt[(size_t)k * HH + hrow] * ps[k];
    g_tp[b * HH + hrow] = acc;
}

__global__ void k_score(const float* __restrict__ h, const int* __restrict__ pred,
                        const float* __restrict__ bbp, float* __restrict__ out)
{
    int b = blockIdx.x;
    int tid = threadIdx.x;
    __shared__ __align__(16) float tps[HH];
    __shared__ float sc[PPG];
    tps[tid] = g_tp[b * HH + tid];
    __syncthreads();
    int warp = tid >> 5, lane = tid & 31;
    float4 tv = ((const float4*)tps)[lane];
    for (int p = warp; p < PPG; p += 4) {
        int node = pred[b * PPG + p];
        float4 hv = ((const float4*)h)[(size_t)node * 32 + lane];
        float d = hv.x * tv.x + hv.y * tv.y + hv.z * tv.z + hv.w * tv.w;
#pragma unroll
        for (int o = 16; o > 0; o >>= 1) d += __shfl_xor_sync(0xffffffffu, d, o);
        if (lane == 0) sc[p] = d + bbp[0];
    }
    __syncthreads();
    if (tid < 32) {
        float v = sc[tid];
        float m = v;
#pragma unroll
        for (int o = 16; o > 0; o >>= 1) m = fmaxf(m, __shfl_xor_sync(0xffffffffu, m, o));
        float e = expf(v - m);
        float s = e;
#pragma unroll
        for (int o = 16; o > 0; o >>= 1) s += __shfl_xor_sync(0xffffffffu, s, o);
        out[b * PPG + tid] = v - m - logf(s);
    }
}

// ---------------- launch ----------------
extern "C" void kernel_launch(void* const* d_in, const int* in_sizes, int n_in,
                              void* d_out, int out_size)
{
    (void)in_sizes; (void)n_in; (void)out_size;
    const float* emb_table = (const float*)d_in[0];
    const float* W_t       = (const float*)d_in[1];
    const float* b_t       = (const float*)d_in[2];
    const float* W_r       = (const float*)d_in[3];
    const float* b_r       = (const float*)d_in[4];
    const float* Wb        = (const float*)d_in[5];
    const float* bb        = (const float*)d_in[6];
    const float* norm      = (const float*)d_in[7];
    const int*   gid       = (const int*)d_in[8];
    const int*   spo       = (const int*)d_in[9];
    const int*   access_   = (const int*)d_in[10];
    const int*   pre       = (const int*)d_in[11];
    const int*   src       = (const int*)d_in[12];
    const int*   dst       = (const int*)d_in[13];
    const int*   etype     = (const int*)d_in[14];
    const int*   pred      = (const int*)d_in[15];
    float* out = (float*)d_out;

    void *p_cnt, *p_h, *p_h2, *p_hb, *p_mh, *p_wh;
    cudaGetSymbolAddress(&p_cnt, g_cnt);
    cudaGetSymbolAddress(&p_h,   g_h);
    cudaGetSymbolAddress(&p_h2,  g_h2);
    cudaGetSymbolAddress(&p_hb,  g_hb);
    cudaGetSymbolAddress(&p_mh,  g_mh);
    cudaGetSymbolAddress(&p_wh,  g_wh);

    const int TPB = 256;
    const int node_warp_blocks = NN / 8;
    const int gemm_blocks      = NN / 128;
    const int proj_blocks      = VPAD / 128;

    cudaFuncSetAttribute(k_proj,   cudaFuncAttributeMaxDynamicSharedMemorySize, SM_TOT);
    cudaFuncSetAttribute(k_gemm_l, cudaFuncAttributeMaxDynamicSharedMemorySize, GL_TOT);

    // --- CSR build + weight cast + table projection ---
    cudaMemsetAsync(p_cnt, 0, (size_t)NN * sizeof(int), 0);
    k_count<<<EE / TPB, TPB>>>(dst);
    k_wsplit<<<(2 * 4 * HH * HH) / TPB, TPB>>>(W_r);
    k_proj<<<proj_blocks, TPB, SM_TOT>>>(emb_table, W_t);
    k_scan1<<<128, 256>>>();
    k_scan2<<<1, 128>>>();
    k_scan3<<<128, 256>>>();
    k_fill<<<EE / TPB, TPB>>>(src, dst, etype, norm);

    // --- init: h0 (fp32 + bf16 mirror) ---
    k_init2<<<node_warp_blocks, TPB>>>(gid, spo, access_, pre, W_t, b_t, (float*)p_h);

    // --- layer 0 ---
    k_gather4<<<node_warp_blocks, TPB>>>();
    k_gemm_l<<<gemm_blocks, TPB, GL_TOT>>>((const uint16_t*)p_mh, (const uint16_t*)p_wh,
                                           b_r, (const float*)p_h, (float*)p_h2,
                                           (uint16_t*)p_hb);

    // --- layer 1 ---
    k_gather4<<<node_warp_blocks, TPB>>>();
    k_gemm_l<<<gemm_blocks, TPB, GL_TOT>>>((const uint16_t*)p_mh,
                                           (const uint16_t*)p_wh + 4 * HH * HH,
                                           b_r + HH, nullptr, (float*)p_h, nullptr);

    // --- head ---
    k_transpose<<<(HH * HH) / TPB, TPB>>>(Wb);
    k_pool<<<BBG, HH>>>((const float*)p_h, pred);
    k_tp<<<BBG, HH>>>();
    k_score<<<BBG, HH>>>((const float*)p_h, pred, bb, out);
}

// round 16
// speedup vs baseline: 1.6933x; 1.1670x over previous
#include <cuda_runtime.h>
#include <cuda_bf16.h>
#include <cstdint>

#define NN   131072
#define EE   1048576
#define HH   128
#define VV   30000
#define VPAD 30080     // 235 * 128
#define BBG  512
#define PPG  32
#define NH   (NN*HH)

// ---------------- static device scratch ----------------
__device__ float g_ptab[VPAD * HH];    // projected embedding table (fp32)
__device__ uint16_t g_ptb[VPAD * HH];  // bf16 mirror of ptab
__device__ float g_h[NH];              // final h (fp32, layer-1 output only)
__device__ uint16_t g_hb[NH];          // bf16 mirror of current h
__device__ uint16_t g_mh[4ULL * NH];   // mailbox (bf16, single plane)
__device__ uint16_t g_wh[2 * 4 * HH * HH];  // W_r (bf16, single plane)
__device__ float g_pool[BBG * HH];
__device__ float g_tp[BBG * HH];
__device__ float g_wbt[HH * HH];
// dst-keyed CSR
__device__ int  g_cnt[NN];
__device__ int  g_off[NN + 1];
__device__ int  g_cur[NN];
__device__ int  g_bsum[128];
__device__ int2 g_rec[EE];             // {src | etype<<20, norm bits}

// ---------------- helpers ----------------
__device__ __forceinline__ uint32_t smem_u32(const void* p) {
    uint32_t a;
    asm("{ .reg .u64 t; cvta.to.shared.u64 t, %1; cvt.u32.u64 %0, t; }" : "=r"(a) : "l"(p));
    return a;
}
__device__ __forceinline__ void ldsm_x4(uint32_t r[4], uint32_t addr) {
    asm volatile("ldmatrix.sync.aligned.m8n8.x4.shared.b16 {%0,%1,%2,%3}, [%4];"
                 : "=r"(r[0]), "=r"(r[1]), "=r"(r[2]), "=r"(r[3]) : "r"(addr));
}
__device__ __forceinline__ void ldsm_x4_t(uint32_t r[4], uint32_t addr) {
    asm volatile("ldmatrix.sync.aligned.m8n8.x4.trans.shared.b16 {%0,%1,%2,%3}, [%4];"
                 : "=r"(r[0]), "=r"(r[1]), "=r"(r[2]), "=r"(r[3]) : "r"(addr));
}
__device__ __forceinline__ void mma_bf16(float* c, const uint32_t a[4], const uint32_t* b) {
    asm volatile(
        "mma.sync.aligned.m16n8k16.row.col.f32.bf16.bf16.f32 "
        "{%0,%1,%2,%3}, {%4,%5,%6,%7}, {%8,%9}, {%0,%1,%2,%3};"
        : "+f"(c[0]), "+f"(c[1]), "+f"(c[2]), "+f"(c[3])
        : "r"(a[0]), "r"(a[1]), "r"(a[2]), "r"(a[3]), "r"(b[0]), "r"(b[1]));
}
__device__ __forceinline__ void split2(float a, float b, uint32_t& hi, uint32_t& lo) {
    __nv_bfloat16 ha = __float2bfloat16_rn(a);
    __nv_bfloat16 hb = __float2bfloat16_rn(b);
    __nv_bfloat16 la = __float2bfloat16_rn(a - __bfloat162float(ha));
    __nv_bfloat16 lb = __float2bfloat16_rn(b - __bfloat162float(hb));
    hi = (uint32_t)__bfloat16_as_ushort(ha) | ((uint32_t)__bfloat16_as_ushort(hb) << 16);
    lo = (uint32_t)__bfloat16_as_ushort(la) | ((uint32_t)__bfloat16_as_ushort(lb) << 16);
}
__device__ __forceinline__ uint32_t pack_bf16(float a, float b) {
    __nv_bfloat162 p = __floats2bfloat162_rn(a, b);
    return *reinterpret_cast<uint32_t*>(&p);
}
__device__ __forceinline__ void cp16_ef(uint32_t smem, const void* g, uint64_t pol) {
    asm volatile("cp.async.cg.shared.global.L2::cache_hint [%0], [%1], 16, %2;"
                 :: "r"(smem), "l"(g), "l"(pol));
}
__device__ __forceinline__ void cp16(uint32_t smem, const void* g) {
    asm volatile("cp.async.cg.shared.global [%0], [%1], 16;" :: "r"(smem), "l"(g));
}

// ---------------- CSR build (dst-keyed) ----------------
__global__ void k_count(const int* __restrict__ dst) {
    int e = blockIdx.x * blockDim.x + threadIdx.x;
    if (e >= EE) return;
    atomicAdd(&g_cnt[dst[e]], 1);
}

__global__ void k_scan1() {
    __shared__ int s[256];
    int t = threadIdx.x;
    int4 v = *(const int4*)(g_cnt + blockIdx.x * 1024 + t * 4);
    s[t] = v.x + v.y + v.z + v.w;
    __syncthreads();
    for (int o = 128; o > 0; o >>= 1) {
        if (t < o) s[t] += s[t + o];
        __syncthreads();
    }
    if (t == 0) g_bsum[blockIdx.x] = s[0];
}

__global__ void k_scan2() {
    __shared__ int s[128];
    int t = threadIdx.x;
    int mine = g_bsum[t];
    s[t] = mine;
    __syncthreads();
    for (int o = 1; o < 128; o <<= 1) {
        int add = (t >= o) ? s[t - o] : 0;
        __syncthreads();
        s[t] += add;
        __syncthreads();
    }
    g_bsum[t] = s[t] - mine;
}

__global__ void k_scan3() {
    __shared__ int s[256];
    int t = threadIdx.x;
    int base = blockIdx.x * 1024 + t * 4;
    int4 v = *(const int4*)(g_cnt + base);
    int tsum = v.x + v.y + v.z + v.w;
    s[t] = tsum;
    __syncthreads();
    for (int o = 1; o < 256; o <<= 1) {
        int add = (t >= o) ? s[t - o] : 0;
        __syncthreads();
        s[t] += add;
        __syncthreads();
    }
    int o0 = s[t] - tsum + g_bsum[blockIdx.x];
    int o1 = o0 + v.x, o2 = o1 + v.y, o3 = o2 + v.z;
    *(int4*)(g_off + base) = make_int4(o0, o1, o2, o3);
    *(int4*)(g_cur + base) = make_int4(o0, o1, o2, o3);
    if (base + 4 == NN) g_off[NN] = o3 + v.w;
}

__global__ void k_fill(const int* __restrict__ src, const int* __restrict__ dst,
                       const int* __restrict__ et,  const float* __restrict__ norm) {
    int e = blockIdx.x * blockDim.x + threadIdx.x;
    if (e >= EE) return;
    int p = atomicAdd(&g_cur[dst[e]], 1);
    g_rec[p] = make_int2(src[e] | (et[e] << 20), __float_as_int(norm[e]));
}

// ---------------- weight cast (bf16 single plane) ----------------
__global__ void k_wsplit(const float* __restrict__ Wr) {
    int i = blockIdx.x * blockDim.x + threadIdx.x;
    g_wh[i] = __bfloat16_as_ushort(__float2bfloat16_rn(Wr[i]));
}

// ---------------- projected table: ptab = emb_table @ Wt[:128] ----------------
#define SM_AHI 0
#define SM_ALO 18432
#define SM_BHI 36864
#define SM_BLO 54272
#define SM_TOT 71680

__global__ void __launch_bounds__(256, 2) k_proj(
    const float* __restrict__ A, const float* __restrict__ Wt)
{
    extern __shared__ char smem[];
    uint32_t s0 = smem_u32(smem);
    int tid = threadIdx.x, wid = tid >> 5, lane = tid & 31;
    int row0 = blockIdx.x * 128;
    int warp_m = wid & 1, warp_n = wid >> 1;

    float c[4][4][4];
#pragma unroll
    for (int i = 0; i < 4; i++)
#pragma unroll
        for (int j = 0; j < 4; j++)
#pragma unroll
            for (int q = 0; q < 4; q++) c[i][j][q] = 0.0f;

    for (int ch = 0; ch < 2; ch++) {
        if (tid < 128) {
#pragma unroll
            for (int p = 0; p < 16; p++) {
                int e = p * 128 + tid;
                int r = e >> 4, c4 = e & 15;
                int rg = min(row0 + r, VV - 1);
                float4 v = *(const float4*)(A + (size_t)rg * HH + ch * 64 + c4 * 4);
                uint32_t h0, l0, h1, l1;
                split2(v.x, v.y, h0, l0);
                split2(v.z, v.w, h1, l1);
                uint32_t off = (uint32_t)r * 144 + c4 * 8;
                *(uint2*)(smem + SM_AHI + off) = make_uint2(h0, h1);
                *(uint2*)(smem + SM_ALO + off) = make_uint2(l0, l1);
            }
        } else {
            int t = tid - 128;
            const float* gb = Wt + (size_t)(ch * 64) * HH;
#pragma unroll
            for (int p = 0; p < 16; p++) {
                int e = p * 128 + t;
                int k = e >> 5, c4 = e & 31;
                float4 v = *(const float4*)(gb + (size_t)k * HH + c4 * 4);
                uint32_t h0, l0, h1, l1;
                split2(v.x, v.y, h0, l0);
                split2(v.z, v.w, h1, l1);
                uint32_t off = (uint32_t)k * 272 + c4 * 8;
                *(uint2*)(smem + SM_BHI + off) = make_uint2(h0, h1);
                *(uint2*)(smem + SM_BLO + off) = make_uint2(l0, l1);
            }
        }
        __syncthreads();

#pragma unroll
        for (int ks = 0; ks < 4; ks++) {
            uint32_t ah[4][4], al[4][4];
#pragma unroll
            for (int mt = 0; mt < 4; mt++) {
                uint32_t row  = warp_m * 64 + mt * 16 + (lane & 15);
                uint32_t addr = s0 + SM_AHI + row * 144 + ks * 32 + ((lane >> 4) << 4);
                ldsm_x4(ah[mt], addr);
                ldsm_x4(al[mt], addr + (SM_ALO - SM_AHI));
            }
#pragma unroll
            for (int np = 0; np < 2; np++) {
                uint32_t kk   = ks * 16 + (lane & 15);
                uint32_t col  = warp_n * 32 + np * 16 + ((lane >> 4) & 1) * 8;
                uint32_t addr = s0 + SM_BHI + kk * 272 + col * 2;
                uint32_t bh[4], bl[4];
                ldsm_x4_t(bh, addr);
                ldsm_x4_t(bl, addr + (SM_BLO - SM_BHI));
#pragma unroll
                for (int mt = 0; mt < 4; mt++) {
                    mma_bf16(c[mt][np * 2],     ah[mt], bh);
                    mma_bf16(c[mt][np * 2],     al[mt], bh);
                    mma_bf16(c[mt][np * 2],     ah[mt], bl);
                    mma_bf16(c[mt][np * 2 + 1], ah[mt], bh + 2);
                    mma_bf16(c[mt][np * 2 + 1], al[mt], bh + 2);
                    mma_bf16(c[mt][np * 2 + 1], ah[mt], bl + 2);
                }
            }
        }
        __syncthreads();
    }

#pragma unroll
    for (int mt = 0; mt < 4; mt++) {
#pragma unroll
        for (int nt = 0; nt < 4; nt++) {
            int col = warp_n * 32 + nt * 8 + (lane & 3) * 2;
#pragma unroll
            for (int half = 0; half < 2; half++) {
                long row = row0 + warp_m * 64 + mt * 16 + (lane >> 2) + half * 8;
                if (row < VV) {
                    float2 v = make_float2(c[mt][nt][half * 2 + 0], c[mt][nt][half * 2 + 1]);
                    *(float2*)(g_ptab + row * HH + col) = v;
                    *(uint32_t*)(g_ptb + row * HH + col) = pack_bf16(v.x, v.y);
                }
            }
        }
    }
}

// ---------------- init: h0 (bf16 mirror only) from ptab ----------------
__global__ void k_init2(const int* __restrict__ gid, const int* __restrict__ spo,
                        const int* __restrict__ acc_, const int* __restrict__ pre,
                        const float* __restrict__ Wt, const float* __restrict__ bt)
{
    __shared__ float sw[768];
    for (int i = threadIdx.x; i < 768; i += blockDim.x)
        sw[i] = (i < 640) ? Wt[(size_t)(128 + (i >> 7)) * HH + (i & 127)] : bt[i - 640];
    __syncthreads();

    int node = (blockIdx.x * blockDim.x + threadIdx.x) >> 5;
    int lane = threadIdx.x & 31;
    if (node >= NN) return;
    int s0 = spo[node * 3 + 0];
    int s1 = spo[node * 3 + 1];
    int s2 = spo[node * 3 + 2];
    int beg = g_off[node], end = g_off[node + 1];

    float4 a = make_float4(0.f, 0.f, 0.f, 0.f);
    bool has_ne = false;
    for (int base = beg; base < end; base += 32) {
        int n = min(32, end - base);
        int2 r = (base + lane < end) ? __ldcs(&g_rec[base + lane]) : make_int2(-1, 0);
        for (int i = 0; i < n; i++) {
            int rx = __shfl_sync(0xffffffffu, r.x, i);
            int rn = __shfl_sync(0xffffffffu, r.y, i);
            if ((rx >> 20) != 0) continue;
            has_ne = true;
            int s = rx & 0xFFFFF;
            float nw = __int_as_float(rn);
            uint2 pv = ((const uint2*)g_ptb)[(size_t)gid[s] * 32 + lane];
            float2 f0 = __bfloat1622float2(*reinterpret_cast<__nv_bfloat162*>(&pv.x));
            float2 f1 = __bfloat1622float2(*reinterpret_cast<__nv_bfloat162*>(&pv.y));
            a.x += f0.x * nw; a.y += f0.y * nw;
            a.z += f1.x * nw; a.w += f1.y * nw;
        }
    }
    float4 e4;
    if ((s0 + s2) > 0 && has_ne) e4 = a;
    else                         e4 = ((const float4*)g_ptab)[(size_t)gid[node] * 32 + lane];

    float cf0 = (float)s0, cf1 = (float)s1, cf2 = (float)s2;
    float cf3 = (float)acc_[node], cf4 = (float)pre[node];
    int col = lane * 4;
#pragma unroll
    for (int q = 0; q < 4; q++) {
        float add = sw[640 + col + q]
                  + cf0 * sw[col + q]       + cf1 * sw[128 + col + q]
                  + cf2 * sw[256 + col + q] + cf3 * sw[384 + col + q]
                  + cf4 * sw[512 + col + q];
        (&e4.x)[q] += add;
    }
    size_t o = (size_t)node * 32 + lane;
    ((uint2*)g_hb)[o] = make_uint2(pack_bf16(e4.x, e4.y), pack_bf16(e4.z, e4.w));
}

// ---------------- gather-first: bf16 h reads, single-plane mailbox ------------
__global__ void k_gather4()
{
    int node = (blockIdx.x * blockDim.x + threadIdx.x) >> 5;
    int lane = threadIdx.x & 31;
    if (node >= NN) return;
    int beg = g_off[node], end = g_off[node + 1];

    float4 a0 = make_float4(0.f, 0.f, 0.f, 0.f);
    float4 a1 = a0, a2 = a0, a3 = a0;
    for (int base = beg; base < end; base += 32) {
        int n = min(32, end - base);
        int2 r = (base + lane < end) ? __ldcs(&g_rec[base + lane]) : make_int2(0, 0);
        for (int i = 0; i < n; i++) {
            int rx = __shfl_sync(0xffffffffu, r.x, i);
            int rn = __shfl_sync(0xffffffffu, r.y, i);
            int s = rx & 0xFFFFF;
            int t = rx >> 20;
            float nw = __int_as_float(rn);
            uint2 pv = ((const uint2*)g_hb)[(size_t)s * 32 + lane];
            float2 f0 = __bfloat1622float2(*reinterpret_cast<__nv_bfloat162*>(&pv.x));
            float2 f1 = __bfloat1622float2(*reinterpret_cast<__nv_bfloat162*>(&pv.y));
            switch (t) {
            case 0: a0.x += f0.x*nw; a0.y += f0.y*nw; a0.z += f1.x*nw; a0.w += f1.y*nw; break;
            case 1: a1.x += f0.x*nw; a1.y += f0.y*nw; a1.z += f1.x*nw; a1.w += f1.y*nw; break;
            case 2: a2.x += f0.x*nw; a2.y += f0.y*nw; a2.z += f1.x*nw; a2.w += f1.y*nw; break;
            default:a3.x += f0.x*nw; a3.y += f0.y*nw; a3.z += f1.x*nw; a3.w += f1.y*nw; break;
            }
        }
    }
    size_t o = (size_t)node * 32 + lane;
    float4 acc[4] = {a0, a1, a2, a3};
#pragma unroll
    for (int t = 0; t < 4; t++) {
        unsigned long long ph =
            (unsigned long long)pack_bf16(acc[t].x, acc[t].y)
          | ((unsigned long long)pack_bf16(acc[t].z, acc[t].w) << 32);
        __stcs((unsigned long long*)(g_mh + (size_t)t * NH) + o, ph);
    }
}

// ---------------- layer GEMM: plain bf16, 3-stage cp.async pipeline ----------
#define GL_AHI 0
#define GL_BHI 10240
#define GL_BUF 18944
#define GL_TOT (3 * GL_BUF)

__global__ void __launch_bounds__(256, 2) k_gemm_l(
    const uint16_t* __restrict__ mh, const uint16_t* __restrict__ wh,
    const float* __restrict__ bias, const uint16_t* __restrict__ residb,
    float* __restrict__ C, uint16_t* __restrict__ hb_out)
{
    extern __shared__ char smem[];
    uint32_t s0 = smem_u32(smem);
    int tid = threadIdx.x, wid = tid >> 5, lane = tid & 31;
    int row0 = blockIdx.x * 128;
    int warp_m = wid & 1, warp_n = wid >> 1;

    uint64_t pol;
    asm("createpolicy.fractional.L2::evict_first.b64 %0, 1.0;" : "=l"(pol));

    float c[4][4][4];
#pragma unroll
    for (int i = 0; i < 4; i++)
#pragma unroll
        for (int j = 0; j < 4; j++)
#pragma unroll
            for (int q = 0; q < 4; q++) c[i][j][q] = 0.0f;

    auto load_chunk = [&](int ch, int buf) {
        int t = ch >> 2, sub = ch & 3;
        const uint16_t* mhb = mh + (size_t)t * NH + (size_t)row0 * HH + sub * 32;
        const uint16_t* whb = wh + (size_t)t * HH * HH + (size_t)(sub * 32) * HH;
        uint32_t sb = s0 + buf * GL_BUF;
#pragma unroll
        for (int q = 0; q < 2; q++) {
            int s = q * 256 + tid;
            int r = s >> 2, part = s & 3;
            cp16_ef(sb + GL_AHI + r * 80 + part * 16, mhb + (size_t)r * HH + part * 8, pol);
        }
#pragma unroll
        for (int q = 0; q < 2; q++) {
            int s = q * 256 + tid;
            int r = s >> 4, part = s & 15;
            cp16(sb + GL_BHI + r * 272 + part * 16, whb + (size_t)r * HH + part * 8);
        }
    };

    load_chunk(0, 0);
    asm volatile("cp.async.commit_group;" ::: "memory");
    load_chunk(1, 1);
    asm volatile("cp.async.commit_group;" ::: "memory");

    for (int ch = 0; ch < 16; ch++) {
        if (ch + 2 < 16) {
            load_chunk(ch + 2, (ch + 2) % 3);
            asm volatile("cp.async.commit_group;" ::: "memory");
            asm volatile("cp.async.wait_group 2;" ::: "memory");
        } else if (ch + 1 < 16) {
            asm volatile("cp.async.wait_group 1;" ::: "memory");
        } else {
            asm volatile("cp.async.wait_group 0;" ::: "memory");
        }
        __syncthreads();

        uint32_t sb = s0 + (ch % 3) * GL_BUF;
#pragma unroll
        for (int ks = 0; ks < 2; ks++) {
            uint32_t ah[4][4];
#pragma unroll
            for (int mt = 0; mt < 4; mt++) {
                uint32_t row  = warp_m * 64 + mt * 16 + (lane & 15);
                uint32_t addr = sb + GL_AHI + row * 80 + ks * 32 + ((lane >> 4) << 4);
                ldsm_x4(ah[mt], addr);
            }
#pragma unroll
            for (int np = 0; np < 2; np++) {
                uint32_t kk   = ks * 16 + (lane & 15);
                uint32_t col  = warp_n * 32 + np * 16 + ((lane >> 4) & 1) * 8;
                uint32_t addr = sb + GL_BHI + kk * 272 + col * 2;
                uint32_t bh[4];
                ldsm_x4_t(bh, addr);
#pragma unroll
                for (int mt = 0; mt < 4; mt++) {
                    mma_bf16(c[mt][np * 2],     ah[mt], bh);
                    mma_bf16(c[mt][np * 2 + 1], ah[mt], bh + 2);
                }
            }
        }
        __syncthreads();
    }

#pragma unroll
    for (int mt = 0; mt < 4; mt++) {
#pragma unroll
        for (int nt = 0; nt < 4; nt++) {
            int col = warp_n * 32 + nt * 8 + (lane & 3) * 2;
            float2 bv = *(const float2*)(bias + col);
#pragma unroll
            for (int half = 0; half < 2; half++) {
                long row  = row0 + warp_m * 64 + mt * 16 + (lane >> 2) + half * 8;
                long base = row * HH + col;
                float2 v;
                v.x = fmaxf(c[mt][nt][half * 2 + 0] + bv.x, 0.f);
                v.y = fmaxf(c[mt][nt][half * 2 + 1] + bv.y, 0.f);
                if (residb) {
                    uint32_t rr = *(const uint32_t*)(residb + base);
                    float2 rf = __bfloat1622float2(*reinterpret_cast<__nv_bfloat162*>(&rr));
                    v.x += rf.x; v.y += rf.y;
                }
                if (C) *(float2*)(C + base) = v;
                if (hb_out)
                    *(uint32_t*)(hb_out + base) = pack_bf16(v.x, v.y);
            }
        }
    }
}

// ---------------- head kernels ----------------
__global__ void k_transpose(const float* __restrict__ Wb) {
    int idx = blockIdx.x * blockDim.x + threadIdx.x;
    if (idx >= HH * HH) return;
    int r = idx >> 7, c = idx & 127;
    g_wbt[c * HH + r] = Wb[idx];
}

__global__ void k_pool(const float* __restrict__ h, const int* __restrict__ pred) {
    int b = blockIdx.x, j = threadIdx.x;
    float acc = 0.0f;
#pragma unroll 4
    for (int p = 0; p < PPG; p++) {
        int node = pred[b * PPG + p];
        acc += h[(size_t)node * HH + j];
    }
    g_pool[b * HH + j] = acc * (1.0f / PPG);
}

__global__ void k_tp() {
    int b = blockIdx.x, hrow = threadIdx.x;
    __shared__ float ps[HH];
    ps[hrow] = g_pool[b * HH + hrow];
    __syncthreads();
    float acc = 0.0f;
#pragma unroll 8
    for (int k = 0; k < HH; k++)
        acc += g_wbt[(size_t)k * HH + hrow] * ps[k];
    g_tp[b * HH + hrow] = acc;
}

__global__ void k_score(const float* __restrict__ h, const int* __restrict__ pred,
                        const float* __restrict__ bbp, float* __restrict__ out)
{
    int b = blockIdx.x;
    int tid = threadIdx.x;
    __shared__ __align__(16) float tps[HH];
    __shared__ float sc[PPG];
    tps[tid] = g_tp[b * HH + tid];
    __syncthreads();
    int warp = tid >> 5, lane = tid & 31;
    float4 tv = ((const float4*)tps)[lane];
    for (int p = warp; p < PPG; p += 4) {
        int node = pred[b * PPG + p];
        float4 hv = ((const float4*)h)[(size_t)node * 32 + lane];
        float d = hv.x * tv.x + hv.y * tv.y + hv.z * tv.z + hv.w * tv.w;
#pragma unroll
        for (int o = 16; o > 0; o >>= 1) d += __shfl_xor_sync(0xffffffffu, d, o);
        if (lane == 0) sc[p] = d + bbp[0];
    }
    __syncthreads();
    if (tid < 32) {
        float v = sc[tid];
        float m = v;
#pragma unroll
        for (int o = 16; o > 0; o >>= 1) m = fmaxf(m, __shfl_xor_sync(0xffffffffu, m, o));
        float e = expf(v - m);
        float s = e;
#pragma unroll
        for (int o = 16; o > 0; o >>= 1) s += __shfl_xor_sync(0xffffffffu, s, o);
        out[b * PPG + tid] = v - m - logf(s);
    }
}

// ---------------- launch ----------------
extern "C" void kernel_launch(void* const* d_in, const int* in_sizes, int n_in,
                              void* d_out, int out_size)
{
    (void)in_sizes; (void)n_in; (void)out_size;
    const float* emb_table = (const float*)d_in[0];
    const float* W_t       = (const float*)d_in[1];
    const float* b_t       = (const float*)d_in[2];
    const float* W_r       = (const float*)d_in[3];
    const float* b_r       = (const float*)d_in[4];
    const float* Wb        = (const float*)d_in[5];
    const float* bb        = (const float*)d_in[6];
    const float* norm      = (const float*)d_in[7];
    const int*   gid       = (const int*)d_in[8];
    const int*   spo       = (const int*)d_in[9];
    const int*   access_   = (const int*)d_in[10];
    const int*   pre       = (const int*)d_in[11];
    const int*   src       = (const int*)d_in[12];
    const int*   dst       = (const int*)d_in[13];
    const int*   etype     = (const int*)d_in[14];
    const int*   pred      = (const int*)d_in[15];
    float* out = (float*)d_out;

    void *p_cnt, *p_h, *p_hb, *p_mh, *p_wh;
    cudaGetSymbolAddress(&p_cnt, g_cnt);
    cudaGetSymbolAddress(&p_h,   g_h);
    cudaGetSymbolAddress(&p_hb,  g_hb);
    cudaGetSymbolAddress(&p_mh,  g_mh);
    cudaGetSymbolAddress(&p_wh,  g_wh);

    const int TPB = 256;
    const int node_warp_blocks = NN / 8;
    const int gemm_blocks      = NN / 128;
    const int proj_blocks      = VPAD / 128;

    cudaFuncSetAttribute(k_proj,   cudaFuncAttributeMaxDynamicSharedMemorySize, SM_TOT);
    cudaFuncSetAttribute(k_gemm_l, cudaFuncAttributeMaxDynamicSharedMemorySize, GL_TOT);

    // --- CSR build + weight cast + table projection ---
    cudaMemsetAsync(p_cnt, 0, (size_t)NN * sizeof(int), 0);
    k_count<<<EE / TPB, TPB>>>(dst);
    k_wsplit<<<(2 * 4 * HH * HH) / TPB, TPB>>>(W_r);
    k_proj<<<proj_blocks, TPB, SM_TOT>>>(emb_table, W_t);
    k_scan1<<<128, 256>>>();
    k_scan2<<<1, 128>>>();
    k_scan3<<<128, 256>>>();
    k_fill<<<EE / TPB, TPB>>>(src, dst, etype, norm);

    // --- init: h0 bf16 mirror only ---
    k_init2<<<node_warp_blocks, TPB>>>(gid, spo, access_, pre, W_t, b_t);

    // --- layer 0: resid from bf16 h0, output only bf16 mirror ---
    k_gather4<<<node_warp_blocks, TPB>>>();
    k_gemm_l<<<gemm_blocks, TPB, GL_TOT>>>((const uint16_t*)p_mh, (const uint16_t*)p_wh,
                                           b_r, (const uint16_t*)p_hb,
                                           nullptr, (uint16_t*)p_hb);

    // --- layer 1: no resid, fp32 output for head ---
    k_gather4<<<node_warp_blocks, TPB>>>();
    k_gemm_l<<<gemm_blocks, TPB, GL_TOT>>>((const uint16_t*)p_mh,
                                           (const uint16_t*)p_wh + 4 * HH * HH,
                                           b_r + HH, nullptr, (float*)p_h, nullptr);

    // --- head ---
    k_transpose<<<(HH * HH) / TPB, TPB>>>(Wb);
    k_pool<<<BBG, HH>>>((const float*)p_h, pred);
    k_tp<<<BBG, HH>>>();
    k_score<<<BBG, HH>>>((const float*)p_h, pred, bb, out);
}

// round 17
// speedup vs baseline: 2.2443x; 1.3254x over previous
#include <cuda_runtime.h>
#include <cuda_bf16.h>
#include <cstdint>

#define NN   131072
#define EE   1048576
#define HH   128
#define VV   30000
#define VPAD 30080     // 235 * 128
#define BBG  512
#define PPG  32
#define NP   (BBG*PPG)         // 16384 predicate nodes
#define NH   (NN*HH)
#define NPH  (NP*HH)

// ---------------- static device scratch ----------------
__device__ float g_ptab[VPAD * HH];    // projected embedding table (fp32)
__device__ uint16_t g_ptb[VPAD * HH];  // bf16 mirror of ptab
__device__ float g_hs[NPH];            // final h at predicate rows (fp32, compact)
__device__ uint16_t g_hb[NH];          // bf16 mirror of current h
__device__ uint16_t g_mh[4ULL * NH];   // full mailbox (bf16) - layer 0
__device__ uint16_t g_mp[4ULL * NPH];  // compact mailbox (bf16) - layer 1
__device__ uint16_t g_wh[2 * 4 * HH * HH];  // W_r (bf16)
__device__ float g_pool[BBG * HH];
__device__ float g_tp[BBG * HH];
__device__ float g_wbt[HH * HH];
// dst-keyed CSR
__device__ int  g_cnt[NN];
__device__ int  g_off[NN + 1];
__device__ int  g_cur[NN];
__device__ int  g_bsum[128];
__device__ int2 g_rec[EE];             // {src | etype<<20, norm bits}

// ---------------- helpers ----------------
__device__ __forceinline__ uint32_t smem_u32(const void* p) {
    uint32_t a;
    asm("{ .reg .u64 t; cvta.to.shared.u64 t, %1; cvt.u32.u64 %0, t; }" : "=r"(a) : "l"(p));
    return a;
}
__device__ __forceinline__ void ldsm_x4(uint32_t r[4], uint32_t addr) {
    asm volatile("ldmatrix.sync.aligned.m8n8.x4.shared.b16 {%0,%1,%2,%3}, [%4];"
                 : "=r"(r[0]), "=r"(r[1]), "=r"(r[2]), "=r"(r[3]) : "r"(addr));
}
__device__ __forceinline__ void ldsm_x4_t(uint32_t r[4], uint32_t addr) {
    asm volatile("ldmatrix.sync.aligned.m8n8.x4.trans.shared.b16 {%0,%1,%2,%3}, [%4];"
                 : "=r"(r[0]), "=r"(r[1]), "=r"(r[2]), "=r"(r[3]) : "r"(addr));
}
__device__ __forceinline__ void mma_bf16(float* c, const uint32_t a[4], const uint32_t* b) {
    asm volatile(
        "mma.sync.aligned.m16n8k16.row.col.f32.bf16.bf16.f32 "
        "{%0,%1,%2,%3}, {%4,%5,%6,%7}, {%8,%9}, {%0,%1,%2,%3};"
        : "+f"(c[0]), "+f"(c[1]), "+f"(c[2]), "+f"(c[3])
        : "r"(a[0]), "r"(a[1]), "r"(a[2]), "r"(a[3]), "r"(b[0]), "r"(b[1]));
}
__device__ __forceinline__ void split2(float a, float b, uint32_t& hi, uint32_t& lo) {
    __nv_bfloat16 ha = __float2bfloat16_rn(a);
    __nv_bfloat16 hb = __float2bfloat16_rn(b);
    __nv_bfloat16 la = __float2bfloat16_rn(a - __bfloat162float(ha));
    __nv_bfloat16 lb = __float2bfloat16_rn(b - __bfloat162float(hb));
    hi = (uint32_t)__bfloat16_as_ushort(ha) | ((uint32_t)__bfloat16_as_ushort(hb) << 16);
    lo = (uint32_t)__bfloat16_as_ushort(la) | ((uint32_t)__bfloat16_as_ushort(lb) << 16);
}
__device__ __forceinline__ uint32_t pack_bf16(float a, float b) {
    __nv_bfloat162 p = __floats2bfloat162_rn(a, b);
    return *reinterpret_cast<uint32_t*>(&p);
}
__device__ __forceinline__ void cp16_ef(uint32_t smem, const void* g, uint64_t pol) {
    asm volatile("cp.async.cg.shared.global.L2::cache_hint [%0], [%1], 16, %2;"
                 :: "r"(smem), "l"(g), "l"(pol));
}
__device__ __forceinline__ void cp16(uint32_t smem, const void* g) {
    asm volatile("cp.async.cg.shared.global [%0], [%1], 16;" :: "r"(smem), "l"(g));
}

// ---------------- CSR build (dst-keyed) ----------------
__global__ void k_count(const int* __restrict__ dst) {
    int e = blockIdx.x * blockDim.x + threadIdx.x;
    if (e >= EE) return;
    atomicAdd(&g_cnt[dst[e]], 1);
}

__global__ void k_scan1() {
    __shared__ int s[256];
    int t = threadIdx.x;
    int4 v = *(const int4*)(g_cnt + blockIdx.x * 1024 + t * 4);
    s[t] = v.x + v.y + v.z + v.w;
    __syncthreads();
    for (int o = 128; o > 0; o >>= 1) {
        if (t < o) s[t] += s[t + o];
        __syncthreads();
    }
    if (t == 0) g_bsum[blockIdx.x] = s[0];
}

__global__ void k_scan2() {
    __shared__ int s[128];
    int t = threadIdx.x;
    int mine = g_bsum[t];
    s[t] = mine;
    __syncthreads();
    for (int o = 1; o < 128; o <<= 1) {
        int add = (t >= o) ? s[t - o] : 0;
        __syncthreads();
        s[t] += add;
        __syncthreads();
    }
    g_bsum[t] = s[t] - mine;
}

__global__ void k_scan3() {
    __shared__ int s[256];
    int t = threadIdx.x;
    int base = blockIdx.x * 1024 + t * 4;
    int4 v = *(const int4*)(g_cnt + base);
    int tsum = v.x + v.y + v.z + v.w;
    s[t] = tsum;
    __syncthreads();
    for (int o = 1; o < 256; o <<= 1) {
        int add = (t >= o) ? s[t - o] : 0;
        __syncthreads();
        s[t] += add;
        __syncthreads();
    }
    int o0 = s[t] - tsum + g_bsum[blockIdx.x];
    int o1 = o0 + v.x, o2 = o1 + v.y, o3 = o2 + v.z;
    *(int4*)(g_off + base) = make_int4(o0, o1, o2, o3);
    *(int4*)(g_cur + base) = make_int4(o0, o1, o2, o3);
    if (base + 4 == NN) g_off[NN] = o3 + v.w;
}

__global__ void k_fill(const int* __restrict__ src, const int* __restrict__ dst,
                       const int* __restrict__ et,  const float* __restrict__ norm) {
    int e = blockIdx.x * blockDim.x + threadIdx.x;
    if (e >= EE) return;
    int p = atomicAdd(&g_cur[dst[e]], 1);
    g_rec[p] = make_int2(src[e] | (et[e] << 20), __float_as_int(norm[e]));
}

// ---------------- weight cast ----------------
__global__ void k_wsplit(const float* __restrict__ Wr) {
    int i = blockIdx.x * blockDim.x + threadIdx.x;
    g_wh[i] = __bfloat16_as_ushort(__float2bfloat16_rn(Wr[i]));
}

// ---------------- projected table: ptab = emb_table @ Wt[:128] ----------------
#define SM_AHI 0
#define SM_ALO 18432
#define SM_BHI 36864
#define SM_BLO 54272
#define SM_TOT 71680

__global__ void __launch_bounds__(256, 2) k_proj(
    const float* __restrict__ A, const float* __restrict__ Wt)
{
    extern __shared__ char smem[];
    uint32_t s0 = smem_u32(smem);
    int tid = threadIdx.x, wid = tid >> 5, lane = tid & 31;
    int row0 = blockIdx.x * 128;
    int warp_m = wid & 1, warp_n = wid >> 1;

    float c[4][4][4];
#pragma unroll
    for (int i = 0; i < 4; i++)
#pragma unroll
        for (int j = 0; j < 4; j++)
#pragma unroll
            for (int q = 0; q < 4; q++) c[i][j][q] = 0.0f;

    for (int ch = 0; ch < 2; ch++) {
        if (tid < 128) {
#pragma unroll
            for (int p = 0; p < 16; p++) {
                int e = p * 128 + tid;
                int r = e >> 4, c4 = e & 15;
                int rg = min(row0 + r, VV - 1);
                float4 v = *(const float4*)(A + (size_t)rg * HH + ch * 64 + c4 * 4);
                uint32_t h0, l0, h1, l1;
                split2(v.x, v.y, h0, l0);
                split2(v.z, v.w, h1, l1);
                uint32_t off = (uint32_t)r * 144 + c4 * 8;
                *(uint2*)(smem + SM_AHI + off) = make_uint2(h0, h1);
                *(uint2*)(smem + SM_ALO + off) = make_uint2(l0, l1);
            }
        } else {
            int t = tid - 128;
            const float* gb = Wt + (size_t)(ch * 64) * HH;
#pragma unroll
            for (int p = 0; p < 16; p++) {
                int e = p * 128 + t;
                int k = e >> 5, c4 = e & 31;
                float4 v = *(const float4*)(gb + (size_t)k * HH + c4 * 4);
                uint32_t h0, l0, h1, l1;
                split2(v.x, v.y, h0, l0);
                split2(v.z, v.w, h1, l1);
                uint32_t off = (uint32_t)k * 272 + c4 * 8;
                *(uint2*)(smem + SM_BHI + off) = make_uint2(h0, h1);
                *(uint2*)(smem + SM_BLO + off) = make_uint2(l0, l1);
            }
        }
        __syncthreads();

#pragma unroll
        for (int ks = 0; ks < 4; ks++) {
            uint32_t ah[4][4], al[4][4];
#pragma unroll
            for (int mt = 0; mt < 4; mt++) {
                uint32_t row  = warp_m * 64 + mt * 16 + (lane & 15);
                uint32_t addr = s0 + SM_AHI + row * 144 + ks * 32 + ((lane >> 4) << 4);
                ldsm_x4(ah[mt], addr);
                ldsm_x4(al[mt], addr + (SM_ALO - SM_AHI));
            }
#pragma unroll
            for (int np = 0; np < 2; np++) {
                uint32_t kk   = ks * 16 + (lane & 15);
                uint32_t col  = warp_n * 32 + np * 16 + ((lane >> 4) & 1) * 8;
                uint32_t addr = s0 + SM_BHI + kk * 272 + col * 2;
                uint32_t bh[4], bl[4];
                ldsm_x4_t(bh, addr);
                ldsm_x4_t(bl, addr + (SM_BLO - SM_BHI));
#pragma unroll
                for (int mt = 0; mt < 4; mt++) {
                    mma_bf16(c[mt][np * 2],     ah[mt], bh);
                    mma_bf16(c[mt][np * 2],     al[mt], bh);
                    mma_bf16(c[mt][np * 2],     ah[mt], bl);
                    mma_bf16(c[mt][np * 2 + 1], ah[mt], bh + 2);
                    mma_bf16(c[mt][np * 2 + 1], al[mt], bh + 2);
                    mma_bf16(c[mt][np * 2 + 1], ah[mt], bl + 2);
                }
            }
        }
        __syncthreads();
    }

#pragma unroll
    for (int mt = 0; mt < 4; mt++) {
#pragma unroll
        for (int nt = 0; nt < 4; nt++) {
            int col = warp_n * 32 + nt * 8 + (lane & 3) * 2;
#pragma unroll
            for (int half = 0; half < 2; half++) {
                long row = row0 + warp_m * 64 + mt * 16 + (lane >> 2) + half * 8;
                if (row < VV) {
                    float2 v = make_float2(c[mt][nt][half * 2 + 0], c[mt][nt][half * 2 + 1]);
                    *(float2*)(g_ptab + row * HH + col) = v;
                    *(uint32_t*)(g_ptb + row * HH + col) = pack_bf16(v.x, v.y);
                }
            }
        }
    }
}

// ---------------- init: h0 (bf16 mirror only) from ptab ----------------
__global__ void k_init2(const int* __restrict__ gid, const int* __restrict__ spo,
                        const int* __restrict__ acc_, const int* __restrict__ pre,
                        const float* __restrict__ Wt, const float* __restrict__ bt)
{
    __shared__ float sw[768];
    for (int i = threadIdx.x; i < 768; i += blockDim.x)
        sw[i] = (i < 640) ? Wt[(size_t)(128 + (i >> 7)) * HH + (i & 127)] : bt[i - 640];
    __syncthreads();

    int node = (blockIdx.x * blockDim.x + threadIdx.x) >> 5;
    int lane = threadIdx.x & 31;
    if (node >= NN) return;
    int s0 = spo[node * 3 + 0];
    int s1 = spo[node * 3 + 1];
    int s2 = spo[node * 3 + 2];
    int beg = g_off[node], end = g_off[node + 1];

    float4 a = make_float4(0.f, 0.f, 0.f, 0.f);
    bool has_ne = false;
    for (int base = beg; base < end; base += 32) {
        int n = min(32, end - base);
        int2 r = (base + lane < end) ? __ldcs(&g_rec[base + lane]) : make_int2(-1, 0);
        for (int i = 0; i < n; i++) {
            int rx = __shfl_sync(0xffffffffu, r.x, i);
            int rn = __shfl_sync(0xffffffffu, r.y, i);
            if ((rx >> 20) != 0) continue;
            has_ne = true;
            int s = rx & 0xFFFFF;
            float nw = __int_as_float(rn);
            uint2 pv = ((const uint2*)g_ptb)[(size_t)gid[s] * 32 + lane];
            float2 f0 = __bfloat1622float2(*reinterpret_cast<__nv_bfloat162*>(&pv.x));
            float2 f1 = __bfloat1622float2(*reinterpret_cast<__nv_bfloat162*>(&pv.y));
            a.x += f0.x * nw; a.y += f0.y * nw;
            a.z += f1.x * nw; a.w += f1.y * nw;
        }
    }
    float4 e4;
    if ((s0 + s2) > 0 && has_ne) e4 = a;
    else                         e4 = ((const float4*)g_ptab)[(size_t)gid[node] * 32 + lane];

    float cf0 = (float)s0, cf1 = (float)s1, cf2 = (float)s2;
    float cf3 = (float)acc_[node], cf4 = (float)pre[node];
    int col = lane * 4;
#pragma unroll
    for (int q = 0; q < 4; q++) {
        float add = sw[640 + col + q]
                  + cf0 * sw[col + q]       + cf1 * sw[128 + col + q]
                  + cf2 * sw[256 + col + q] + cf3 * sw[384 + col + q]
                  + cf4 * sw[512 + col + q];
        (&e4.x)[q] += add;
    }
    size_t o = (size_t)node * 32 + lane;
    ((uint2*)g_hb)[o] = make_uint2(pack_bf16(e4.x, e4.y), pack_bf16(e4.z, e4.w));
}

// ---------------- gather: full (layer 0) ----------------
__global__ void k_gather4()
{
    int node = (blockIdx.x * blockDim.x + threadIdx.x) >> 5;
    int lane = threadIdx.x & 31;
    if (node >= NN) return;
    int beg = g_off[node], end = g_off[node + 1];

    float4 a0 = make_float4(0.f, 0.f, 0.f, 0.f);
    float4 a1 = a0, a2 = a0, a3 = a0;
    for (int base = beg; base < end; base += 32) {
        int n = min(32, end - base);
        int2 r = (base + lane < end) ? __ldcs(&g_rec[base + lane]) : make_int2(0, 0);
        for (int i = 0; i < n; i++) {
            int rx = __shfl_sync(0xffffffffu, r.x, i);
            int rn = __shfl_sync(0xffffffffu, r.y, i);
            int s = rx & 0xFFFFF;
            int t = rx >> 20;
            float nw = __int_as_float(rn);
            uint2 pv = ((const uint2*)g_hb)[(size_t)s * 32 + lane];
            float2 f0 = __bfloat1622float2(*reinterpret_cast<__nv_bfloat162*>(&pv.x));
            float2 f1 = __bfloat1622float2(*reinterpret_cast<__nv_bfloat162*>(&pv.y));
            switch (t) {
            case 0: a0.x += f0.x*nw; a0.y += f0.y*nw; a0.z += f1.x*nw; a0.w += f1.y*nw; break;
            case 1: a1.x += f0.x*nw; a1.y += f0.y*nw; a1.z += f1.x*nw; a1.w += f1.y*nw; break;
            case 2: a2.x += f0.x*nw; a2.y += f0.y*nw; a2.z += f1.x*nw; a2.w += f1.y*nw; break;
            default:a3.x += f0.x*nw; a3.y += f0.y*nw; a3.z += f1.x*nw; a3.w += f1.y*nw; break;
            }
        }
    }
    size_t o = (size_t)node * 32 + lane;
    float4 acc[4] = {a0, a1, a2, a3};
#pragma unroll
    for (int t = 0; t < 4; t++) {
        unsigned long long ph =
            (unsigned long long)pack_bf16(acc[t].x, acc[t].y)
          | ((unsigned long long)pack_bf16(acc[t].z, acc[t].w) << 32);
        __stcs((unsigned long long*)(g_mh + (size_t)t * NH) + o, ph);
    }
}

// ---------------- gather: predicate-only (layer 1) -> compact mailbox ----------
__global__ void k_gather4p(const int* __restrict__ pred)
{
    int idx  = (blockIdx.x * blockDim.x + threadIdx.x) >> 5;   // compact id
    int lane = threadIdx.x & 31;
    if (idx >= NP) return;
    int node = pred[idx];
    int beg = g_off[node], end = g_off[node + 1];

    float4 a0 = make_float4(0.f, 0.f, 0.f, 0.f);
    float4 a1 = a0, a2 = a0, a3 = a0;
    for (int base = beg; base < end; base += 32) {
        int n = min(32, end - base);
        int2 r = (base + lane < end) ? __ldcs(&g_rec[base + lane]) : make_int2(0, 0);
        for (int i = 0; i < n; i++) {
            int rx = __shfl_sync(0xffffffffu, r.x, i);
            int rn = __shfl_sync(0xffffffffu, r.y, i);
            int s = rx & 0xFFFFF;
            int t = rx >> 20;
            float nw = __int_as_float(rn);
            uint2 pv = ((const uint2*)g_hb)[(size_t)s * 32 + lane];
            float2 f0 = __bfloat1622float2(*reinterpret_cast<__nv_bfloat162*>(&pv.x));
            float2 f1 = __bfloat1622float2(*reinterpret_cast<__nv_bfloat162*>(&pv.y));
            switch (t) {
            case 0: a0.x += f0.x*nw; a0.y += f0.y*nw; a0.z += f1.x*nw; a0.w += f1.y*nw; break;
            case 1: a1.x += f0.x*nw; a1.y += f0.y*nw; a1.z += f1.x*nw; a1.w += f1.y*nw; break;
            case 2: a2.x += f0.x*nw; a2.y += f0.y*nw; a2.z += f1.x*nw; a2.w += f1.y*nw; break;
            default:a3.x += f0.x*nw; a3.y += f0.y*nw; a3.z += f1.x*nw; a3.w += f1.y*nw; break;
            }
        }
    }
    size_t o = (size_t)idx * 32 + lane;
    float4 acc[4] = {a0, a1, a2, a3};
#pragma unroll
    for (int t = 0; t < 4; t++) {
        unsigned long long ph =
            (unsigned long long)pack_bf16(acc[t].x, acc[t].y)
          | ((unsigned long long)pack_bf16(acc[t].z, acc[t].w) << 32);
        __stcs((unsigned long long*)(g_mp + (size_t)t * NPH) + o, ph);
    }
}

// ---------------- layer GEMM: plain bf16, 3-stage cp.async pipeline ----------
#define GL_AHI 0
#define GL_BHI 10240
#define GL_BUF 18944
#define GL_TOT (3 * GL_BUF)

__global__ void __launch_bounds__(256, 2) k_gemm_l(
    const uint16_t* __restrict__ mh, long plane,
    const uint16_t* __restrict__ wh,
    const float* __restrict__ bias, const uint16_t* __restrict__ residb,
    float* __restrict__ C, uint16_t* __restrict__ hb_out)
{
    extern __shared__ char smem[];
    uint32_t s0 = smem_u32(smem);
    int tid = threadIdx.x, wid = tid >> 5, lane = tid & 31;
    int row0 = blockIdx.x * 128;
    int warp_m = wid & 1, warp_n = wid >> 1;

    uint64_t pol;
    asm("createpolicy.fractional.L2::evict_first.b64 %0, 1.0;" : "=l"(pol));

    float c[4][4][4];
#pragma unroll
    for (int i = 0; i < 4; i++)
#pragma unroll
        for (int j = 0; j < 4; j++)
#pragma unroll
            for (int q = 0; q < 4; q++) c[i][j][q] = 0.0f;

    auto load_chunk = [&](int ch, int buf) {
        int t = ch >> 2, sub = ch & 3;
        const uint16_t* mhb = mh + (size_t)t * plane + (size_t)row0 * HH + sub * 32;
        const uint16_t* whb = wh + (size_t)t * HH * HH + (size_t)(sub * 32) * HH;
        uint32_t sb = s0 + buf * GL_BUF;
#pragma unroll
        for (int q = 0; q < 2; q++) {
            int s = q * 256 + tid;
            int r = s >> 2, part = s & 3;
            cp16_ef(sb + GL_AHI + r * 80 + part * 16, mhb + (size_t)r * HH + part * 8, pol);
        }
#pragma unroll
        for (int q = 0; q < 2; q++) {
            int s = q * 256 + tid;
            int r = s >> 4, part = s & 15;
            cp16(sb + GL_BHI + r * 272 + part * 16, whb + (size_t)r * HH + part * 8);
        }
    };

    load_chunk(0, 0);
    asm volatile("cp.async.commit_group;" ::: "memory");
    load_chunk(1, 1);
    asm volatile("cp.async.commit_group;" ::: "memory");

    for (int ch = 0; ch < 16; ch++) {
        if (ch + 2 < 16) {
            load_chunk(ch + 2, (ch + 2) % 3);
            asm volatile("cp.async.commit_group;" ::: "memory");
            asm volatile("cp.async.wait_group 2;" ::: "memory");
        } else if (ch + 1 < 16) {
            asm volatile("cp.async.wait_group 1;" ::: "memory");
        } else {
            asm volatile("cp.async.wait_group 0;" ::: "memory");
        }
        __syncthreads();

        uint32_t sb = s0 + (ch % 3) * GL_BUF;
#pragma unroll
        for (int ks = 0; ks < 2; ks++) {
            uint32_t ah[4][4];
#pragma unroll
            for (int mt = 0; mt < 4; mt++) {
                uint32_t row  = warp_m * 64 + mt * 16 + (lane & 15);
                uint32_t addr = sb + GL_AHI + row * 80 + ks * 32 + ((lane >> 4) << 4);
                ldsm_x4(ah[mt], addr);
            }
#pragma unroll
            for (int np = 0; np < 2; np++) {
                uint32_t kk   = ks * 16 + (lane & 15);
                uint32_t col  = warp_n * 32 + np * 16 + ((lane >> 4) & 1) * 8;
                uint32_t addr = sb + GL_BHI + kk * 272 + col * 2;
                uint32_t bh[4];
                ldsm_x4_t(bh, addr);
#pragma unroll
                for (int mt = 0; mt < 4; mt++) {
                    mma_bf16(c[mt][np * 2],     ah[mt], bh);
                    mma_bf16(c[mt][np * 2 + 1], ah[mt], bh + 2);
                }
            }
        }
        __syncthreads();
    }

#pragma unroll
    for (int mt = 0; mt < 4; mt++) {
#pragma unroll
        for (int nt = 0; nt < 4; nt++) {
            int col = warp_n * 32 + nt * 8 + (lane & 3) * 2;
            float2 bv = *(const float2*)(bias + col);
#pragma unroll
            for (int half = 0; half < 2; half++) {
                long row  = row0 + warp_m * 64 + mt * 16 + (lane >> 2) + half * 8;
                long base = row * HH + col;
                float2 v;
                v.x = fmaxf(c[mt][nt][half * 2 + 0] + bv.x, 0.f);
                v.y = fmaxf(c[mt][nt][half * 2 + 1] + bv.y, 0.f);
                if (residb) {
                    uint32_t rr = *(const uint32_t*)(residb + base);
                    float2 rf = __bfloat1622float2(*reinterpret_cast<__nv_bfloat162*>(&rr));
                    v.x += rf.x; v.y += rf.y;
                }
                if (C) *(float2*)(C + base) = v;
                if (hb_out)
                    *(uint32_t*)(hb_out + base) = pack_bf16(v.x, v.y);
            }
        }
    }
}

// ---------------- head kernels (compact h_small) ----------------
__global__ void k_transpose(const float* __restrict__ Wb) {
    int idx = blockIdx.x * blockDim.x + threadIdx.x;
    if (idx >= HH * HH) return;
    int r = idx >> 7, c = idx & 127;
    g_wbt[c * HH + r] = Wb[idx];
}

__global__ void k_pool() {
    int b = blockIdx.x, j = threadIdx.x;
    float acc = 0.0f;
#pragma unroll 4
    for (int p = 0; p < PPG; p++)
        acc += g_hs[(size_t)(b * PPG + p) * HH + j];
    g_pool[b * HH + j] = acc * (1.0f / PPG);
}

__global__ void k_tp() {
    int b = blockIdx.x, hrow = threadIdx.x;
    __shared__ float ps[HH];
    ps[hrow] = g_pool[b * HH + hrow];
    __syncthreads();
    float acc = 0.0f;
#pragma unroll 8
    for (int k = 0; k < HH; k++)
        acc += g_wbt[(size_t)k * HH + hrow] * ps[k];
    g_tp[b * HH + hrow] = acc;
}

__global__ void k_score(const float* __restrict__ bbp, float* __restrict__ out)
{
    int b = blockIdx.x;
    int tid = threadIdx.x;
    __shared__ __align__(16) float tps[HH];
    __shared__ float sc[PPG];
    tps[tid] = g_tp[b * HH + tid];
    __syncthreads();
    int warp = tid >> 5, lane = tid & 31;
    float4 tv = ((const float4*)tps)[lane];
    for (int p = warp; p < PPG; p += 4) {
        float4 hv = ((const float4*)g_hs)[(size_t)(b * PPG + p) * 32 + lane];
        float d = hv.x * tv.x + hv.y * tv.y + hv.z * tv.z + hv.w * tv.w;
#pragma unroll
        for (int o = 16; o > 0; o >>= 1) d += __shfl_xor_sync(0xffffffffu, d, o);
        if (lane == 0) sc[p] = d + bbp[0];
    }
    __syncthreads();
    if (tid < 32) {
        float v = sc[tid];
        float m = v;
#pragma unroll
        for (int o = 16; o > 0; o >>= 1) m = fmaxf(m, __shfl_xor_sync(0xffffffffu, m, o));
        float e = expf(v - m);
        float s = e;
#pragma unroll
        for (int o = 16; o > 0; o >>= 1) s += __shfl_xor_sync(0xffffffffu, s, o);
        out[b * PPG + tid] = v - m - logf(s);
    }
}

// ---------------- launch ----------------
extern "C" void kernel_launch(void* const* d_in, const int* in_sizes, int n_in,
                              void* d_out, int out_size)
{
    (void)in_sizes; (void)n_in; (void)out_size;
    const float* emb_table = (const float*)d_in[0];
    const float* W_t       = (const float*)d_in[1];
    const float* b_t       = (const float*)d_in[2];
    const float* W_r       = (const float*)d_in[3];
    const float* b_r       = (const float*)d_in[4];
    const float* Wb        = (const float*)d_in[5];
    const float* bb        = (const float*)d_in[6];
    const float* norm      = (const float*)d_in[7];
    const int*   gid       = (const int*)d_in[8];
    const int*   spo       = (const int*)d_in[9];
    const int*   access_   = (const int*)d_in[10];
    const int*   pre       = (const int*)d_in[11];
    const int*   src       = (const int*)d_in[12];
    const int*   dst       = (const int*)d_in[13];
    const int*   etype     = (const int*)d_in[14];
    const int*   pred      = (const int*)d_in[15];
    float* out = (float*)d_out;

    void *p_cnt, *p_hs, *p_hb, *p_mh, *p_mp, *p_wh;
    cudaGetSymbolAddress(&p_cnt, g_cnt);
    cudaGetSymbolAddress(&p_hs,  g_hs);
    cudaGetSymbolAddress(&p_hb,  g_hb);
    cudaGetSymbolAddress(&p_mh,  g_mh);
    cudaGetSymbolAddress(&p_mp,  g_mp);
    cudaGetSymbolAddress(&p_wh,  g_wh);

    const int TPB = 256;
    const int node_warp_blocks = NN / 8;
    const int pred_warp_blocks = NP / 8;
    const int gemm_blocks      = NN / 128;
    const int gemm_blocks_p    = NP / 128;     // 128
    const int proj_blocks      = VPAD / 128;

    cudaFuncSetAttribute(k_proj,   cudaFuncAttributeMaxDynamicSharedMemorySize, SM_TOT);
    cudaFuncSetAttribute(k_gemm_l, cudaFuncAttributeMaxDynamicSharedMemorySize, GL_TOT);

    // --- CSR build + weight cast + table projection ---
    cudaMemsetAsync(p_cnt, 0, (size_t)NN * sizeof(int), 0);
    k_count<<<EE / TPB, TPB>>>(dst);
    k_wsplit<<<(2 * 4 * HH * HH) / TPB, TPB>>>(W_r);
    k_proj<<<proj_blocks, TPB, SM_TOT>>>(emb_table, W_t);
    k_scan1<<<128, 256>>>();
    k_scan2<<<1, 128>>>();
    k_scan3<<<128, 256>>>();
    k_fill<<<EE / TPB, TPB>>>(src, dst, etype, norm);

    // --- init: h0 bf16 mirror ---
    k_init2<<<node_warp_blocks, TPB>>>(gid, spo, access_, pre, W_t, b_t);

    // --- layer 0: full graph ---
    k_gather4<<<node_warp_blocks, TPB>>>();
    k_gemm_l<<<gemm_blocks, TPB, GL_TOT>>>((const uint16_t*)p_mh, (long)NH,
                                           (const uint16_t*)p_wh,
                                           b_r, (const uint16_t*)p_hb,
                                           nullptr, (uint16_t*)p_hb);

    // --- layer 1: predicate rows only (compact) ---
    k_gather4p<<<pred_warp_blocks, TPB>>>(pred);
    k_gemm_l<<<gemm_blocks_p, TPB, GL_TOT>>>((const uint16_t*)p_mp, (long)NPH,
                                             (const uint16_t*)p_wh + 4 * HH * HH,
                                             b_r + HH, nullptr,
                                             (float*)p_hs, nullptr);

    // --- head ---
    k_transpose<<<(HH * HH) / TPB, TPB>>>(Wb);
    k_pool<<<BBG, HH>>>();
    k_tp<<<BBG, HH>>>();
    k_score<<<BBG, HH>>>(bb, out);
}